// round 1
// baseline (speedup 1.0000x reference)
#include <cuda_runtime.h>
#include <math.h>
#include <float.h>

#define BB 8
#define TT 2048
#define EE 128
#define HH 256
#define BT (BB*TT)

#define BM 64
#define BN 32
#define KP 260   // padded row length (floats) for 256-wide tiles: 2*KP*4 mod 128B = 32 -> 2-way LDS.128 conflicts max
#define PP 36    // padded row length for P tile

// scratch for projected Q,K,V (device globals: allocation-free)
__device__ float g_Q[BT*HH];
__device__ float g_K[BT*HH];
__device__ float g_V[BT*HH];

// ---------------------------------------------------------------------------
// QKV projection: out[z][row, col] = x[row,:] @ W[z][:, col] + bias[z][col]
// Block tile: 64 rows x 64 cols, full K=128. blockIdx.z selects Q/K/V.
// ---------------------------------------------------------------------------
__global__ __launch_bounds__(256, 1) void proj_kernel(
    const float* __restrict__ x,
    const float* __restrict__ Wq, const float* __restrict__ bq,
    const float* __restrict__ Wk, const float* __restrict__ bk,
    const float* __restrict__ Wv, const float* __restrict__ bv)
{
    extern __shared__ float sm[];
    float* Xs = sm;              // [64][128]
    float* Ws = sm + 64 * EE;    // [128][64]

    const int bn = blockIdx.x;       // 0..3   (col tile of 64)
    const int bm = blockIdx.y;       // 0..255 (row tile of 64)
    const int z  = blockIdx.z;       // 0..2
    const float* W    = (z == 0) ? Wq : ((z == 1) ? Wk : Wv);
    const float* bias = (z == 0) ? bq : ((z == 1) ? bk : bv);
    float* out        = (z == 0) ? g_Q : ((z == 1) ? g_K : g_V);

    const int tid = threadIdx.x;

    // Load X tile [64][128] (coalesced float4 copy)
    {
        const float4* src = reinterpret_cast<const float4*>(x + (size_t)bm * 64 * EE);
        float4* dst = reinterpret_cast<float4*>(Xs);
        #pragma unroll
        for (int i = 0; i < 8; i++) dst[tid + i * 256] = src[tid + i * 256];
    }
    // Load W tile [128][64] (cols bn*64 .. bn*64+63), k-major
    #pragma unroll
    for (int i = 0; i < 8; i++) {
        int s  = tid + i * 256;       // float4 slot, 2048 total
        int k  = s >> 4;              // 16 float4 per k-row
        int n4 = (s & 15) * 4;
        *reinterpret_cast<float4*>(&Ws[k * 64 + n4]) =
            *reinterpret_cast<const float4*>(&W[k * HH + bn * 64 + n4]);
    }
    __syncthreads();

    const int tx = tid & 15;   // n dim (4 cols each)
    const int ty = tid >> 4;   // m dim (4 rows each)

    float acc[4][4];
    #pragma unroll
    for (int j = 0; j < 4; j++)
        #pragma unroll
        for (int c = 0; c < 4; c++) acc[j][c] = 0.0f;

    #pragma unroll 4
    for (int k = 0; k < EE; k += 4) {
        float4 a[4], b[4];
        #pragma unroll
        for (int j = 0; j < 4; j++)
            a[j] = *reinterpret_cast<const float4*>(&Xs[(ty * 4 + j) * EE + k]);
        #pragma unroll
        for (int i = 0; i < 4; i++)
            b[i] = *reinterpret_cast<const float4*>(&Ws[(k + i) * 64 + tx * 4]);
        #pragma unroll
        for (int j = 0; j < 4; j++) {
            const float* aj = reinterpret_cast<const float*>(&a[j]);
            #pragma unroll
            for (int i = 0; i < 4; i++) {
                const float av = aj[i];
                const float* bi = reinterpret_cast<const float*>(&b[i]);
                acc[j][0] += av * bi[0];
                acc[j][1] += av * bi[1];
                acc[j][2] += av * bi[2];
                acc[j][3] += av * bi[3];
            }
        }
    }

    const float4 b4 = *reinterpret_cast<const float4*>(&bias[bn * 64 + tx * 4]);
    #pragma unroll
    for (int j = 0; j < 4; j++) {
        const int row = bm * 64 + ty * 4 + j;
        float4 o;
        o.x = acc[j][0] + b4.x;
        o.y = acc[j][1] + b4.y;
        o.z = acc[j][2] + b4.z;
        o.w = acc[j][3] + b4.w;
        *reinterpret_cast<float4*>(&out[(size_t)row * HH + bn * 64 + tx * 4]) = o;
    }
}

// ---------------------------------------------------------------------------
// Flash attention (fp32, causal): one block = 64 query rows of one batch.
// Iterates key tiles of 32, online softmax, O accumulator in registers.
// Threads: 256 (tx = tid&15 owns 16 output cols; ty = tid>>4 owns 4 rows).
// ---------------------------------------------------------------------------
__global__ __launch_bounds__(256, 1) void flash_kernel(float* __restrict__ out)
{
    extern __shared__ float sm[];
    float* Qs = sm;                      // [64][KP]
    float* Ks = Qs + BM * KP;            // [32][KP]
    float* Vs = Ks + BN * KP;            // [32][KP]
    float* Ps = Vs + BN * KP;            // [64][PP]

    const int qt  = (int)(gridDim.x - 1) - (int)blockIdx.x;  // heavy tiles first
    const int b   = blockIdx.y;
    const int tid = threadIdx.x;
    const int tx  = tid & 15;
    const int ty  = tid >> 4;

    // Load Q tile [64][256]
    {
        const float* Qg = g_Q + (size_t)(b * TT + qt * BM) * HH;
        #pragma unroll
        for (int i = 0; i < 16; i++) {
            int s  = tid + i * 256;     // float4 slot, 4096 total
            int r  = s >> 6;            // 64 float4 per row
            int c4 = (s & 63) * 4;
            *reinterpret_cast<float4*>(&Qs[r * KP + c4]) =
                *reinterpret_cast<const float4*>(&Qg[r * HH + c4]);
        }
    }

    float4 o4[4][4];
    #pragma unroll
    for (int j = 0; j < 4; j++)
        #pragma unroll
        for (int i4 = 0; i4 < 4; i4++) o4[j][i4] = make_float4(0.f, 0.f, 0.f, 0.f);

    float m_i[4], l_i[4];
    #pragma unroll
    for (int j = 0; j < 4; j++) { m_i[j] = -3.0e38f; l_i[j] = 0.0f; }

    const float LOG2E = 1.4426950408889634f;
    const float scale = 0.0625f;   // 1/sqrt(256)

    const int ktmax = 2 * qt + 1;
    for (int kt = 0; kt <= ktmax; ++kt) {
        __syncthreads();   // previous iteration done with Ks/Vs/Ps
        {
            const float* Kg = g_K + (size_t)(b * TT + kt * BN) * HH;
            const float* Vg = g_V + (size_t)(b * TT + kt * BN) * HH;
            #pragma unroll
            for (int i = 0; i < 8; i++) {
                int s  = tid + i * 256;   // 2048 float4 slots
                int r  = s >> 6;
                int c4 = (s & 63) * 4;
                *reinterpret_cast<float4*>(&Ks[r * KP + c4]) =
                    *reinterpret_cast<const float4*>(&Kg[r * HH + c4]);
                *reinterpret_cast<float4*>(&Vs[r * KP + c4]) =
                    *reinterpret_cast<const float4*>(&Vg[r * HH + c4]);
            }
        }
        __syncthreads();

        // ---- S = Q K^T, thread tile 4x2 ----
        float sa[4][2];
        #pragma unroll
        for (int j = 0; j < 4; j++) { sa[j][0] = 0.f; sa[j][1] = 0.f; }

        #pragma unroll 2
        for (int d = 0; d < HH; d += 4) {
            float4 a[4], kb[2];
            #pragma unroll
            for (int j = 0; j < 4; j++)
                a[j] = *reinterpret_cast<const float4*>(&Qs[(ty * 4 + j) * KP + d]);
            #pragma unroll
            for (int i = 0; i < 2; i++)
                kb[i] = *reinterpret_cast<const float4*>(&Ks[(tx * 2 + i) * KP + d]);
            #pragma unroll
            for (int j = 0; j < 4; j++) {
                const float* aj = reinterpret_cast<const float*>(&a[j]);
                const float* k0 = reinterpret_cast<const float*>(&kb[0]);
                const float* k1 = reinterpret_cast<const float*>(&kb[1]);
                #pragma unroll
                for (int u = 0; u < 4; u++) {
                    sa[j][0] += aj[u] * k0[u];
                    sa[j][1] += aj[u] * k1[u];
                }
            }
        }

        // ---- online softmax ----
        const bool need_mask = (kt >= 2 * qt);
        const int row0 = qt * BM + ty * 4;
        const int col0 = kt * BN + tx * 2;
        float f[4];
        #pragma unroll
        for (int j = 0; j < 4; j++) {
            float v0 = sa[j][0] * scale;
            float v1 = sa[j][1] * scale;
            if (need_mask) {
                if (col0     > row0 + j) v0 = -3.0e38f;
                if (col0 + 1 > row0 + j) v1 = -3.0e38f;
            }
            float mx = fmaxf(v0, v1);
            #pragma unroll
            for (int off = 8; off >= 1; off >>= 1)
                mx = fmaxf(mx, __shfl_xor_sync(0xffffffffu, mx, off));
            const float mn = fmaxf(m_i[j], mx);
            const float fj = exp2f((m_i[j] - mn) * LOG2E);
            m_i[j] = mn;
            const float p0 = exp2f((v0 - mn) * LOG2E);
            const float p1 = exp2f((v1 - mn) * LOG2E);
            Ps[(ty * 4 + j) * PP + tx * 2]     = p0;
            Ps[(ty * 4 + j) * PP + tx * 2 + 1] = p1;
            float ps = p0 + p1;
            #pragma unroll
            for (int off = 8; off >= 1; off >>= 1)
                ps += __shfl_xor_sync(0xffffffffu, ps, off);
            l_i[j] = l_i[j] * fj + ps;
            f[j] = fj;
        }
        // rescale O accumulators
        #pragma unroll
        for (int j = 0; j < 4; j++) {
            #pragma unroll
            for (int i4 = 0; i4 < 4; i4++) {
                o4[j][i4].x *= f[j]; o4[j][i4].y *= f[j];
                o4[j][i4].z *= f[j]; o4[j][i4].w *= f[j];
            }
        }
        __syncthreads();   // Ps visible to all

        // ---- O += P V, thread tile 4 rows x 16 cols (cols tx*16 .. tx*16+15) ----
        #pragma unroll 2
        for (int kk = 0; kk < BN; kk += 4) {
            float4 p4[4];
            #pragma unroll
            for (int j = 0; j < 4; j++)
                p4[j] = *reinterpret_cast<const float4*>(&Ps[(ty * 4 + j) * PP + kk]);
            #pragma unroll
            for (int u = 0; u < 4; u++) {
                float4 v4[4];
                #pragma unroll
                for (int i4 = 0; i4 < 4; i4++)
                    v4[i4] = *reinterpret_cast<const float4*>(
                        &Vs[(kk + u) * KP + tx * 16 + i4 * 4]);
                #pragma unroll
                for (int j = 0; j < 4; j++) {
                    const float pv = reinterpret_cast<const float*>(&p4[j])[u];
                    #pragma unroll
                    for (int i4 = 0; i4 < 4; i4++) {
                        o4[j][i4].x += pv * v4[i4].x;
                        o4[j][i4].y += pv * v4[i4].y;
                        o4[j][i4].z += pv * v4[i4].z;
                        o4[j][i4].w += pv * v4[i4].w;
                    }
                }
            }
        }
    }

    // epilogue: normalize and store
    #pragma unroll
    for (int j = 0; j < 4; j++) {
        const float inv = 1.0f / l_i[j];
        const int row = b * TT + qt * BM + ty * 4 + j;
        #pragma unroll
        for (int i4 = 0; i4 < 4; i4++) {
            float4 o;
            o.x = o4[j][i4].x * inv;
            o.y = o4[j][i4].y * inv;
            o.z = o4[j][i4].z * inv;
            o.w = o4[j][i4].w * inv;
            *reinterpret_cast<float4*>(&out[(size_t)row * HH + tx * 16 + i4 * 4]) = o;
        }
    }
}

// ---------------------------------------------------------------------------
extern "C" void kernel_launch(void* const* d_in, const int* in_sizes, int n_in,
                              void* d_out, int out_size)
{
    const float* x  = (const float*)d_in[0];
    const float* Wq = (const float*)d_in[1];
    const float* bq = (const float*)d_in[2];
    const float* Wk = (const float*)d_in[3];
    const float* bk = (const float*)d_in[4];
    const float* Wv = (const float*)d_in[5];
    const float* bv = (const float*)d_in[6];
    float* out = (float*)d_out;

    const int proj_smem  = (64 * EE + EE * 64) * (int)sizeof(float);           // 64 KB
    const int flash_smem = ((BM + 2 * BN) * KP + BM * PP) * (int)sizeof(float); // ~139 KB

    cudaFuncSetAttribute(proj_kernel,  cudaFuncAttributeMaxDynamicSharedMemorySize, proj_smem);
    cudaFuncSetAttribute(flash_kernel, cudaFuncAttributeMaxDynamicSharedMemorySize, flash_smem);

    proj_kernel<<<dim3(HH / 64, BT / 64, 3), 256, proj_smem>>>(x, Wq, bq, Wk, bk, Wv, bv);
    flash_kernel<<<dim3(TT / BM, BB), 256, flash_smem>>>(out);
}

// round 2
// speedup vs baseline: 4.2105x; 4.2105x over previous
#include <cuda_runtime.h>
#include <math.h>

#define BB 8
#define TT 2048
#define EE 128
#define HH 256
#define BT (BB*TT)

#define BM 64
#define BN 64
#define DP 260      // Qs/Ks row stride (floats): bank = 4g+tg -> conflict-free frags
#define VP 264      // Vs row stride: bank = 8tg+g -> conflict-free B frags
#define PSP 68      // Ps row stride: bank = 4g+tg -> conflict-free A frags

// scratch for projected Q,K,V (tf32-rounded fp32 bits)
__device__ float g_Q[BT*HH];
__device__ float g_K[BT*HH];
__device__ float g_V[BT*HH];

__device__ __forceinline__ unsigned f2tf32(float f) {
    unsigned r;
    asm("cvt.rna.tf32.f32 %0, %1;" : "=r"(r) : "f"(f));
    return r;
}

__device__ __forceinline__ void mma8(float* d, const unsigned* a, unsigned b0, unsigned b1) {
    asm volatile(
        "mma.sync.aligned.m16n8k8.row.col.f32.tf32.tf32.f32 "
        "{%0,%1,%2,%3}, {%4,%5,%6,%7}, {%8,%9}, {%0,%1,%2,%3};"
        : "+f"(d[0]), "+f"(d[1]), "+f"(d[2]), "+f"(d[3])
        : "r"(a[0]), "r"(a[1]), "r"(a[2]), "r"(a[3]), "r"(b0), "r"(b1));
}

// ---------------------------------------------------------------------------
// QKV projection (fp32 FFMA, 64x64x128 tiles); epilogue rounds to tf32.
// ---------------------------------------------------------------------------
__global__ __launch_bounds__(256, 1) void proj_kernel(
    const float* __restrict__ x,
    const float* __restrict__ Wq, const float* __restrict__ bq,
    const float* __restrict__ Wk, const float* __restrict__ bk,
    const float* __restrict__ Wv, const float* __restrict__ bv)
{
    extern __shared__ float sm[];
    float* Xs = sm;              // [64][128]
    float* Ws = sm + 64 * EE;    // [128][64]

    const int bn = blockIdx.x;
    const int bm = blockIdx.y;
    const int z  = blockIdx.z;
    const float* W    = (z == 0) ? Wq : ((z == 1) ? Wk : Wv);
    const float* bias = (z == 0) ? bq : ((z == 1) ? bk : bv);
    float* out        = (z == 0) ? g_Q : ((z == 1) ? g_K : g_V);

    const int tid = threadIdx.x;

    {
        const float4* src = reinterpret_cast<const float4*>(x + (size_t)bm * 64 * EE);
        float4* dst = reinterpret_cast<float4*>(Xs);
        #pragma unroll
        for (int i = 0; i < 8; i++) dst[tid + i * 256] = src[tid + i * 256];
    }
    #pragma unroll
    for (int i = 0; i < 8; i++) {
        int s  = tid + i * 256;
        int k  = s >> 4;
        int n4 = (s & 15) * 4;
        *reinterpret_cast<float4*>(&Ws[k * 64 + n4]) =
            *reinterpret_cast<const float4*>(&W[k * HH + bn * 64 + n4]);
    }
    __syncthreads();

    const int tx = tid & 15;
    const int ty = tid >> 4;

    float acc[4][4];
    #pragma unroll
    for (int j = 0; j < 4; j++)
        #pragma unroll
        for (int c = 0; c < 4; c++) acc[j][c] = 0.0f;

    #pragma unroll 4
    for (int k = 0; k < EE; k += 4) {
        float4 a[4], b[4];
        #pragma unroll
        for (int j = 0; j < 4; j++)
            a[j] = *reinterpret_cast<const float4*>(&Xs[(ty * 4 + j) * EE + k]);
        #pragma unroll
        for (int i = 0; i < 4; i++)
            b[i] = *reinterpret_cast<const float4*>(&Ws[(k + i) * 64 + tx * 4]);
        #pragma unroll
        for (int j = 0; j < 4; j++) {
            const float* aj = reinterpret_cast<const float*>(&a[j]);
            #pragma unroll
            for (int i = 0; i < 4; i++) {
                const float av = aj[i];
                const float* bi = reinterpret_cast<const float*>(&b[i]);
                acc[j][0] += av * bi[0];
                acc[j][1] += av * bi[1];
                acc[j][2] += av * bi[2];
                acc[j][3] += av * bi[3];
            }
        }
    }

    const float4 b4 = *reinterpret_cast<const float4*>(&bias[bn * 64 + tx * 4]);
    #pragma unroll
    for (int j = 0; j < 4; j++) {
        const int row = bm * 64 + ty * 4 + j;
        float4 o;
        o.x = __uint_as_float(f2tf32(acc[j][0] + b4.x));
        o.y = __uint_as_float(f2tf32(acc[j][1] + b4.y));
        o.z = __uint_as_float(f2tf32(acc[j][2] + b4.z));
        o.w = __uint_as_float(f2tf32(acc[j][3] + b4.w));
        *reinterpret_cast<float4*>(&out[(size_t)row * HH + bn * 64 + tx * 4]) = o;
    }
}

// ---------------------------------------------------------------------------
// Flash attention with tf32 mma.sync tensor cores.
// Block: 64 q-rows of one batch, 256 threads (8 warps).
// Stage1 (S=QK^T): warps 2(M)x4(N). Stage2 (O+=PV): warps 2(M)x4(headcols).
// ---------------------------------------------------------------------------
__global__ __launch_bounds__(256, 1) void flash_kernel(float* __restrict__ out)
{
    extern __shared__ float sm[];
    float* Qs = sm;                                   // [64][DP]
    float* Ks = Qs + 64 * DP;                         // [64][DP]
    float* Vs = Ks + 64 * DP;                         // [64][VP]
    unsigned* Ps = (unsigned*)(Vs + 64 * VP);         // [64][PSP] tf32 bits
    float* Smax = (float*)(Ps + 64 * PSP);            // [64][4]
    float* Ssum = Smax + 64 * 4;                      // [64][4]
    float* m_st = Ssum + 64 * 4;                      // [64]
    float* l_st = m_st + 64;                          // [64]
    float* frow = l_st + 64;                          // [64]

    const int qt   = (int)(gridDim.x - 1) - (int)blockIdx.x;  // heavy first
    const int b    = blockIdx.y;
    const int tid  = threadIdx.x;
    const int lane = tid & 31;
    const int wid  = tid >> 5;
    const int g    = lane >> 2;     // groupID (row within frag)
    const int tg   = lane & 3;      // threadID in group
    const int mi   = wid & 1;       // stage1 M warp
    const int ni   = wid >> 1;      // stage1 N warp (0..3)
    const int mi2  = wid & 1;       // stage2 M warp
    const int nh   = wid >> 1;      // stage2 head-col warp (0..3)

    // Load Q tile [64][256] -> Qs (stride DP)
    {
        const float* Qg = g_Q + (size_t)(b * TT + qt * BM) * HH;
        #pragma unroll
        for (int i = 0; i < 16; i++) {
            int s  = tid + i * 256;
            int r  = s >> 6;
            int c4 = (s & 63) * 4;
            *reinterpret_cast<float4*>(&Qs[r * DP + c4]) =
                *reinterpret_cast<const float4*>(&Qg[r * HH + c4]);
        }
    }
    if (tid < 64) { m_st[tid] = -3.0e38f; l_st[tid] = 0.0f; }

    float Oacc[2][8][4];
    #pragma unroll
    for (int mf = 0; mf < 2; mf++)
        #pragma unroll
        for (int nf = 0; nf < 8; nf++)
            #pragma unroll
            for (int c = 0; c < 4; c++) Oacc[mf][nf][c] = 0.0f;

    const float LOG2E = 1.4426950408889634f;
    const float scale = 0.0625f;   // 1/sqrt(256)

    for (int kt = 0; kt <= qt; ++kt) {
        __syncthreads();   // prev iter done with Ks/Vs/Ps; Q load / state init done
        {
            const float* Kg = g_K + (size_t)(b * TT + kt * BN) * HH;
            const float* Vg = g_V + (size_t)(b * TT + kt * BN) * HH;
            #pragma unroll
            for (int i = 0; i < 16; i++) {
                int s  = tid + i * 256;
                int r  = s >> 6;
                int c4 = (s & 63) * 4;
                *reinterpret_cast<float4*>(&Ks[r * DP + c4]) =
                    *reinterpret_cast<const float4*>(&Kg[r * HH + c4]);
                *reinterpret_cast<float4*>(&Vs[r * VP + c4]) =
                    *reinterpret_cast<const float4*>(&Vg[r * HH + c4]);
            }
        }
        __syncthreads();

        // ---- Stage 1: S = Q K^T (warp tile 32x16, k=256) ----
        float Sacc[2][2][4];
        #pragma unroll
        for (int mf = 0; mf < 2; mf++)
            #pragma unroll
            for (int nf = 0; nf < 2; nf++)
                #pragma unroll
                for (int c = 0; c < 4; c++) Sacc[mf][nf][c] = 0.0f;

        {
            const float* Aq = Qs + (mi * 32) * DP;
            const float* Bk = Ks + (ni * 16) * DP;
            #pragma unroll 4
            for (int k = 0; k < HH; k += 8) {
                unsigned a[2][4];
                #pragma unroll
                for (int mf = 0; mf < 2; mf++) {
                    const float* base = Aq + (mf * 16 + g) * DP + k + tg;
                    a[mf][0] = __float_as_uint(base[0]);
                    a[mf][1] = __float_as_uint(base[8 * DP]);
                    a[mf][2] = __float_as_uint(base[4]);
                    a[mf][3] = __float_as_uint(base[8 * DP + 4]);
                }
                #pragma unroll
                for (int nf = 0; nf < 2; nf++) {
                    const float* bb = Bk + (nf * 8 + g) * DP + k + tg;
                    unsigned b0 = __float_as_uint(bb[0]);
                    unsigned b1 = __float_as_uint(bb[4]);
                    mma8(Sacc[0][nf], a[0], b0, b1);
                    mma8(Sacc[1][nf], a[1], b0, b1);
                }
            }
        }

        // ---- scale + causal mask + per-warp row max ----
        const bool diag = (kt == qt);
        const int qrow0 = qt * BM + mi * 32;
        const int kcol0 = kt * BN + ni * 16;
        #pragma unroll
        for (int mf = 0; mf < 2; mf++) {
            float m0 = -3.0e38f, m1 = -3.0e38f;
            #pragma unroll
            for (int nf = 0; nf < 2; nf++) {
                float* s4 = Sacc[mf][nf];
                s4[0] *= scale; s4[1] *= scale; s4[2] *= scale; s4[3] *= scale;
                if (diag) {
                    const int c0 = kcol0 + nf * 8 + tg * 2;
                    const int r0 = qrow0 + mf * 16 + g;
                    if (c0     > r0)     s4[0] = -3.0e38f;
                    if (c0 + 1 > r0)     s4[1] = -3.0e38f;
                    if (c0     > r0 + 8) s4[2] = -3.0e38f;
                    if (c0 + 1 > r0 + 8) s4[3] = -3.0e38f;
                }
                m0 = fmaxf(m0, fmaxf(s4[0], s4[1]));
                m1 = fmaxf(m1, fmaxf(s4[2], s4[3]));
            }
            m0 = fmaxf(m0, __shfl_xor_sync(0xffffffffu, m0, 1));
            m0 = fmaxf(m0, __shfl_xor_sync(0xffffffffu, m0, 2));
            m1 = fmaxf(m1, __shfl_xor_sync(0xffffffffu, m1, 1));
            m1 = fmaxf(m1, __shfl_xor_sync(0xffffffffu, m1, 2));
            if (tg == 0) {
                Smax[(mi * 32 + mf * 16 + g) * 4 + ni]     = m0;
                Smax[(mi * 32 + mf * 16 + g + 8) * 4 + ni] = m1;
            }
        }
        __syncthreads();

        // ---- P = exp(S - m_new), write tf32 to Ps, partial row sums ----
        #pragma unroll
        for (int mf = 0; mf < 2; mf++) {
            #pragma unroll
            for (int h = 0; h < 2; h++) {
                const int row = mi * 32 + mf * 16 + g + h * 8;
                const float mo = m_st[row];
                float mn = fmaxf(fmaxf(Smax[row * 4 + 0], Smax[row * 4 + 1]),
                                 fmaxf(Smax[row * 4 + 2], Smax[row * 4 + 3]));
                mn = fmaxf(mn, mo);
                float psum = 0.0f;
                #pragma unroll
                for (int nf = 0; nf < 2; nf++) {
                    const float* s4 = Sacc[mf][nf];
                    const float p0 = exp2f((s4[2 * h + 0] - mn) * LOG2E);
                    const float p1 = exp2f((s4[2 * h + 1] - mn) * LOG2E);
                    const int colp = ni * 16 + nf * 8 + tg * 2;
                    Ps[row * PSP + colp]     = f2tf32(p0);
                    Ps[row * PSP + colp + 1] = f2tf32(p1);
                    psum += p0 + p1;
                }
                psum += __shfl_xor_sync(0xffffffffu, psum, 1);
                psum += __shfl_xor_sync(0xffffffffu, psum, 2);
                if (tg == 0) Ssum[row * 4 + ni] = psum;
            }
        }
        __syncthreads();

        // ---- warp 0 updates m/l state and rescale factors ----
        if (wid == 0) {
            #pragma unroll
            for (int i = 0; i < 2; i++) {
                const int row = lane + i * 32;
                const float mo = m_st[row];
                float mn = fmaxf(fmaxf(Smax[row * 4 + 0], Smax[row * 4 + 1]),
                                 fmaxf(Smax[row * 4 + 2], Smax[row * 4 + 3]));
                mn = fmaxf(mn, mo);
                const float f = exp2f((mo - mn) * LOG2E);
                l_st[row] = l_st[row] * f +
                            (Ssum[row * 4 + 0] + Ssum[row * 4 + 1] +
                             Ssum[row * 4 + 2] + Ssum[row * 4 + 3]);
                m_st[row] = mn;
                frow[row] = f;
            }
        }
        __syncthreads();

        // ---- Stage 2: O = O*f + P V (warp tile 32 rows x 64 head cols) ----
        {
            const float f00 = frow[mi2 * 32 + g];
            const float f01 = frow[mi2 * 32 + g + 8];
            const float f10 = frow[mi2 * 32 + 16 + g];
            const float f11 = frow[mi2 * 32 + 16 + g + 8];
            #pragma unroll
            for (int nf = 0; nf < 8; nf++) {
                Oacc[0][nf][0] *= f00; Oacc[0][nf][1] *= f00;
                Oacc[0][nf][2] *= f01; Oacc[0][nf][3] *= f01;
                Oacc[1][nf][0] *= f10; Oacc[1][nf][1] *= f10;
                Oacc[1][nf][2] *= f11; Oacc[1][nf][3] *= f11;
            }

            #pragma unroll
            for (int kk = 0; kk < BN; kk += 8) {
                unsigned a[2][4];
                #pragma unroll
                for (int mf = 0; mf < 2; mf++) {
                    const unsigned* base = Ps + (mi2 * 32 + mf * 16 + g) * PSP + kk + tg;
                    a[mf][0] = base[0];
                    a[mf][1] = base[8 * PSP];
                    a[mf][2] = base[4];
                    a[mf][3] = base[8 * PSP + 4];
                }
                #pragma unroll
                for (int nf = 0; nf < 8; nf++) {
                    const int col = nh * 64 + nf * 8 + g;
                    unsigned b0 = __float_as_uint(Vs[(kk + tg) * VP + col]);
                    unsigned b1 = __float_as_uint(Vs[(kk + tg + 4) * VP + col]);
                    mma8(Oacc[0][nf], a[0], b0, b1);
                    mma8(Oacc[1][nf], a[1], b0, b1);
                }
            }
        }
    }

    // ---- epilogue: normalize and store ----
    {
        const float il00 = 1.0f / l_st[mi2 * 32 + g];
        const float il01 = 1.0f / l_st[mi2 * 32 + g + 8];
        const float il10 = 1.0f / l_st[mi2 * 32 + 16 + g];
        const float il11 = 1.0f / l_st[mi2 * 32 + 16 + g + 8];
        float* outp = out + (size_t)(b * TT + qt * BM + mi2 * 32) * HH + nh * 64;
        #pragma unroll
        for (int mf = 0; mf < 2; mf++) {
            const float ilo = mf ? il10 : il00;
            const float ihi = mf ? il11 : il01;
            #pragma unroll
            for (int nf = 0; nf < 8; nf++) {
                const int col = nf * 8 + tg * 2;
                float2 v0, v1;
                v0.x = Oacc[mf][nf][0] * ilo;
                v0.y = Oacc[mf][nf][1] * ilo;
                v1.x = Oacc[mf][nf][2] * ihi;
                v1.y = Oacc[mf][nf][3] * ihi;
                *reinterpret_cast<float2*>(&outp[(mf * 16 + g) * HH + col])     = v0;
                *reinterpret_cast<float2*>(&outp[(mf * 16 + g + 8) * HH + col]) = v1;
            }
        }
    }
}

// ---------------------------------------------------------------------------
extern "C" void kernel_launch(void* const* d_in, const int* in_sizes, int n_in,
                              void* d_out, int out_size)
{
    const float* x  = (const float*)d_in[0];
    const float* Wq = (const float*)d_in[1];
    const float* bq = (const float*)d_in[2];
    const float* Wk = (const float*)d_in[3];
    const float* bk = (const float*)d_in[4];
    const float* Wv = (const float*)d_in[5];
    const float* bv = (const float*)d_in[6];
    float* out = (float*)d_out;

    const int proj_smem = (64 * EE + EE * 64) * (int)sizeof(float);
    const int flash_smem = (64 * DP * 2 + 64 * VP + 64 * PSP + 64 * 4 * 2 + 64 * 3)
                           * (int)sizeof(float);   // ~221 KB

    cudaFuncSetAttribute(proj_kernel,  cudaFuncAttributeMaxDynamicSharedMemorySize, proj_smem);
    cudaFuncSetAttribute(flash_kernel, cudaFuncAttributeMaxDynamicSharedMemorySize, flash_smem);

    proj_kernel<<<dim3(HH / 64, BT / 64, 3), 256, proj_smem>>>(x, Wq, bq, Wk, bk, Wv, bv);
    flash_kernel<<<dim3(TT / BM, BB), 256, flash_smem>>>(out);
}

// round 4
// speedup vs baseline: 9.5238x; 2.2619x over previous
#include <cuda_runtime.h>
#include <cuda_fp16.h>
#include <math.h>

#define BB 8
#define TT 2048
#define EE 128
#define HH 256
#define BT (BB*TT)

#define QP  264    // halves pitch for Q/K/V smem tiles (row step = +4 banks)
#define PSH 72     // halves pitch for P tile
#define XP  136    // halves pitch for proj tiles

// fp16 scratch for projected Q (pre-scaled by log2e/16), K, V
__device__ __half g_Qh[(size_t)BT*HH];
__device__ __half g_Kh[(size_t)BT*HH];
__device__ __half g_Vh[(size_t)BT*HH];

__device__ __forceinline__ unsigned su32(const void* p) {
    return (unsigned)__cvta_generic_to_shared(p);
}
__device__ __forceinline__ void ldsm_x4(unsigned* r, unsigned a) {
    asm volatile("ldmatrix.sync.aligned.m8n8.x4.shared.b16 {%0,%1,%2,%3}, [%4];"
        : "=r"(r[0]), "=r"(r[1]), "=r"(r[2]), "=r"(r[3]) : "r"(a));
}
__device__ __forceinline__ void ldsm_x4t(unsigned* r, unsigned a) {
    asm volatile("ldmatrix.sync.aligned.m8n8.x4.trans.shared.b16 {%0,%1,%2,%3}, [%4];"
        : "=r"(r[0]), "=r"(r[1]), "=r"(r[2]), "=r"(r[3]) : "r"(a));
}
__device__ __forceinline__ void mma16(float* d, const unsigned* a, unsigned b0, unsigned b1) {
    asm volatile("mma.sync.aligned.m16n8k16.row.col.f32.f16.f16.f32 "
        "{%0,%1,%2,%3},{%4,%5,%6,%7},{%8,%9},{%0,%1,%2,%3};"
        : "+f"(d[0]), "+f"(d[1]), "+f"(d[2]), "+f"(d[3])
        : "r"(a[0]), "r"(a[1]), "r"(a[2]), "r"(a[3]), "r"(b0), "r"(b1));
}
__device__ __forceinline__ void cpa16(unsigned d, const void* s) {
    asm volatile("cp.async.cg.shared.global [%0], [%1], 16;" :: "r"(d), "l"(s));
}
#define CP_COMMIT() asm volatile("cp.async.commit_group;")
#define CP_WAIT0()  asm volatile("cp.async.wait_group 0;")

// ---------------------------------------------------------------------------
// Projection: out = fp16( (x @ W + b) * scale ), tile 128 rows x 128 cols.
// Warp layout: mi = wid&1 (64 rows), nj = wid>>1 (32 cols). fp16 mma.
// ---------------------------------------------------------------------------
__global__ __launch_bounds__(256, 1) void proj_kernel(
    const float* __restrict__ x,
    const float* __restrict__ Wq, const float* __restrict__ bq,
    const float* __restrict__ Wk, const float* __restrict__ bk,
    const float* __restrict__ Wv, const float* __restrict__ bv)
{
    extern __shared__ __half sh[];
    __half* Xh = sh;              // [128][XP]
    __half* Wh = sh + 128 * XP;   // [128 k][XP] (128 n cols used)

    const int bn = blockIdx.x;    // 0..1
    const int bm = blockIdx.y;    // 0..127
    const int z  = blockIdx.z;    // 0..2
    const float* W    = (z == 0) ? Wq : ((z == 1) ? Wk : Wv);
    const float* bias = (z == 0) ? bq : ((z == 1) ? bk : bv);
    __half* outp      = (z == 0) ? g_Qh : ((z == 1) ? g_Kh : g_Vh);
    const float scale = (z == 0) ? 0.0901679843431555f : 1.0f;  // log2e/16

    const int tid = threadIdx.x;

    // X tile [128][128] fp32 -> fp16 smem
    {
        const float* Xg = x + (size_t)bm * 128 * EE;
        #pragma unroll
        for (int i = 0; i < 16; i++) {
            int s = tid + i * 256;
            int r = s >> 5;
            int c4 = (s & 31) * 4;
            float4 v = *reinterpret_cast<const float4*>(&Xg[r * EE + c4]);
            *reinterpret_cast<__half2*>(&Xh[r * XP + c4])     = __floats2half2_rn(v.x, v.y);
            *reinterpret_cast<__half2*>(&Xh[r * XP + c4 + 2]) = __floats2half2_rn(v.z, v.w);
        }
    }
    // W tile [128 k][128 n] fp32 -> fp16 smem
    {
        #pragma unroll
        for (int i = 0; i < 16; i++) {
            int s = tid + i * 256;
            int r = s >> 5;
            int c4 = (s & 31) * 4;
            float4 v = *reinterpret_cast<const float4*>(&W[r * HH + bn * 128 + c4]);
            *reinterpret_cast<__half2*>(&Wh[r * XP + c4])     = __floats2half2_rn(v.x, v.y);
            *reinterpret_cast<__half2*>(&Wh[r * XP + c4 + 2]) = __floats2half2_rn(v.z, v.w);
        }
    }
    __syncthreads();

    const int lane = tid & 31;
    const int wid  = tid >> 5;
    const int g    = lane >> 2;
    const int tg   = lane & 3;
    const int mi   = wid & 1;    // rows mi*64
    const int nj   = wid >> 1;   // cols nj*32
    const int lr   = lane & 15;
    const int lc   = (lane >> 4) << 3;

    float acc[4][4][4];
    #pragma unroll
    for (int mf = 0; mf < 4; mf++)
        #pragma unroll
        for (int nf = 0; nf < 4; nf++)
            #pragma unroll
            for (int c = 0; c < 4; c++) acc[mf][nf][c] = 0.0f;

    const unsigned aX = su32(Xh + (mi * 64 + lr) * XP + lc);
    const unsigned aW = su32(Wh + lr * XP + nj * 32 + lc);

    #pragma unroll
    for (int kb = 0; kb < 8; kb++) {
        unsigned a[4][4];
        #pragma unroll
        for (int mf = 0; mf < 4; mf++)
            ldsm_x4(a[mf], aX + (mf * 16 * XP + kb * 16) * 2);
        #pragma unroll
        for (int j = 0; j < 2; j++) {
            unsigned wb[4];
            ldsm_x4t(wb, aW + (kb * 16 * XP + j * 16) * 2);
            #pragma unroll
            for (int mf = 0; mf < 4; mf++) {
                mma16(acc[mf][2 * j],     a[mf], wb[0], wb[1]);
                mma16(acc[mf][2 * j + 1], a[mf], wb[2], wb[3]);
            }
        }
    }

    // epilogue: + bias, * scale, -> fp16
    #pragma unroll
    for (int nf = 0; nf < 4; nf++) {
        const int col = nj * 32 + nf * 8 + 2 * tg;
        const float b0 = bias[bn * 128 + col];
        const float b1 = bias[bn * 128 + col + 1];
        #pragma unroll
        for (int mf = 0; mf < 4; mf++) {
            const int r0 = bm * 128 + mi * 64 + mf * 16 + g;
            __half2 h0 = __floats2half2_rn((acc[mf][nf][0] + b0) * scale,
                                           (acc[mf][nf][1] + b1) * scale);
            __half2 h1 = __floats2half2_rn((acc[mf][nf][2] + b0) * scale,
                                           (acc[mf][nf][3] + b1) * scale);
            *reinterpret_cast<__half2*>(&outp[(size_t)r0 * HH + bn * 128 + col])       = h0;
            *reinterpret_cast<__half2*>(&outp[(size_t)(r0 + 8) * HH + bn * 128 + col]) = h1;
        }
    }
}

// ---------------------------------------------------------------------------
// Flash attention, fp16 mma, cp.async double-buffered K/V.
// Block: 64 q-rows of one batch, 8 warps. mi = wid&1 owns 32 rows in BOTH
// stages; ni/nh = wid>>1 splits 64 S-cols (stage1) / 256 head-cols (stage2).
// m/l state in registers (replicated over the 4 warps sharing rows).
// ---------------------------------------------------------------------------
__global__ __launch_bounds__(256, 1) void flash_kernel(float* __restrict__ out)
{
    extern __shared__ __half sh[];
    __half* Qs = sh;                      // [64][QP]
    __half* Ks = sh + 64 * QP;            // 2 x [64][QP]
    __half* Vs = Ks + 2 * 64 * QP;        // 2 x [64][QP]
    __half* Ps = Vs + 2 * 64 * QP;        // [64][PSH]
    float* Smax = (float*)(Ps + 64 * PSH);  // [64][4]
    float* Ssum = Smax + 256;               // [64][4]

    const int qt   = (int)(gridDim.x - 1) - (int)blockIdx.x;  // heavy first
    const int b    = blockIdx.y;
    const int tid  = threadIdx.x;
    const int lane = tid & 31;
    const int wid  = tid >> 5;
    const int g    = lane >> 2;
    const int tg   = lane & 3;
    const int mi   = wid & 1;
    const int ni   = wid >> 1;     // stage1 col group (16 cols)
    const int nh   = wid >> 1;     // stage2 head-col group (64 cols)
    const int lr   = lane & 15;
    const int lc   = (lane >> 4) << 3;

    // prologue: Q + K0/V0 via cp.async (one group)
    {
        const __half* Qg = g_Qh + (size_t)(b * TT + qt * 64) * HH;
        const __half* Kg = g_Kh + (size_t)(b * TT) * HH;
        const __half* Vg = g_Vh + (size_t)(b * TT) * HH;
        #pragma unroll
        for (int i = 0; i < 8; i++) {
            int s = tid + i * 256;
            int r = s >> 5;
            int c8 = (s & 31) * 8;
            cpa16(su32(Qs + r * QP + c8), Qg + r * HH + c8);
            cpa16(su32(Ks + r * QP + c8), Kg + r * HH + c8);
            cpa16(su32(Vs + r * QP + c8), Vg + r * HH + c8);
        }
        CP_COMMIT();
    }

    float Oacc[2][8][4];
    #pragma unroll
    for (int mf = 0; mf < 2; mf++)
        #pragma unroll
        for (int nf = 0; nf < 8; nf++)
            #pragma unroll
            for (int c = 0; c < 4; c++) Oacc[mf][nf][c] = 0.0f;

    float m_loc[2][2], l_loc[2][2];
    #pragma unroll
    for (int mf = 0; mf < 2; mf++)
        #pragma unroll
        for (int h = 0; h < 2; h++) { m_loc[mf][h] = -1.0e30f; l_loc[mf][h] = 0.0f; }

    for (int kt = 0; kt <= qt; ++kt) {
        CP_WAIT0();
        __syncthreads();   // S0: buffer(kt) visible; prev iteration fully done

        // prefetch next K/V tile into the other buffer
        if (kt < qt) {
            const __half* Kg = g_Kh + (size_t)(b * TT + (kt + 1) * 64) * HH;
            const __half* Vg = g_Vh + (size_t)(b * TT + (kt + 1) * 64) * HH;
            __half* Kd = Ks + ((kt + 1) & 1) * 64 * QP;
            __half* Vd = Vs + ((kt + 1) & 1) * 64 * QP;
            #pragma unroll
            for (int i = 0; i < 8; i++) {
                int s = tid + i * 256;
                int r = s >> 5;
                int c8 = (s & 31) * 8;
                cpa16(su32(Kd + r * QP + c8), Kg + r * HH + c8);
                cpa16(su32(Vd + r * QP + c8), Vg + r * HH + c8);
            }
            CP_COMMIT();
        }

        const __half* Kb = Ks + (kt & 1) * 64 * QP;
        const __half* Vb = Vs + (kt & 1) * 64 * QP;

        // ---- Stage 1: S = Q K^T (warp: 32 rows x 16 cols, k=256) ----
        float Sacc[2][2][4];
        #pragma unroll
        for (int mf = 0; mf < 2; mf++)
            #pragma unroll
            for (int nf = 0; nf < 2; nf++)
                #pragma unroll
                for (int c = 0; c < 4; c++) Sacc[mf][nf][c] = 0.0f;

        {
            const unsigned aA = su32(Qs + (mi * 32 + lr) * QP + lc);
            const unsigned aB = su32(Kb + (ni * 16 + lr) * QP + lc);
            #pragma unroll
            for (int kb = 0; kb < 16; kb++) {
                unsigned a0[4], a1[4], br[4];
                ldsm_x4(a0, aA + (kb * 16) * 2);
                ldsm_x4(a1, aA + (16 * QP + kb * 16) * 2);
                ldsm_x4(br, aB + (kb * 16) * 2);
                mma16(Sacc[0][0], a0, br[0], br[2]);
                mma16(Sacc[0][1], a0, br[1], br[3]);
                mma16(Sacc[1][0], a1, br[0], br[2]);
                mma16(Sacc[1][1], a1, br[1], br[3]);
            }
        }

        // ---- causal mask (diag tile) + per-warp row max -> Smax ----
        if (kt == qt) {
            #pragma unroll
            for (int mf = 0; mf < 2; mf++)
                #pragma unroll
                for (int nf = 0; nf < 2; nf++) {
                    const int col = ni * 16 + nf * 8 + 2 * tg;
                    const int r0  = mi * 32 + mf * 16 + g;
                    if (col     > r0)     Sacc[mf][nf][0] = -1.0e30f;
                    if (col + 1 > r0)     Sacc[mf][nf][1] = -1.0e30f;
                    if (col     > r0 + 8) Sacc[mf][nf][2] = -1.0e30f;
                    if (col + 1 > r0 + 8) Sacc[mf][nf][3] = -1.0e30f;
                }
        }
        #pragma unroll
        for (int mf = 0; mf < 2; mf++) {
            #pragma unroll
            for (int h = 0; h < 2; h++) {
                float mx = fmaxf(fmaxf(Sacc[mf][0][2*h], Sacc[mf][0][2*h+1]),
                                 fmaxf(Sacc[mf][1][2*h], Sacc[mf][1][2*h+1]));
                mx = fmaxf(mx, __shfl_xor_sync(0xffffffffu, mx, 1));
                mx = fmaxf(mx, __shfl_xor_sync(0xffffffffu, mx, 2));
                if (tg == 0)
                    Smax[(mi * 32 + mf * 16 + h * 8 + g) * 4 + ni] = mx;
            }
        }
        __syncthreads();   // S1

        // ---- P = exp2(S - mn) (fp16 to Ps) + partial sums ----
        float mn[2][2];
        #pragma unroll
        for (int mf = 0; mf < 2; mf++) {
            #pragma unroll
            for (int h = 0; h < 2; h++) {
                const int row = mi * 32 + mf * 16 + h * 8 + g;
                float4 s4 = *reinterpret_cast<const float4*>(&Smax[row * 4]);
                float m = fmaxf(fmaxf(s4.x, s4.y), fmaxf(s4.z, s4.w));
                m = fmaxf(m, m_loc[mf][h]);
                mn[mf][h] = m;
                float psum = 0.0f;
                #pragma unroll
                for (int nf = 0; nf < 2; nf++) {
                    const float p0 = exp2f(Sacc[mf][nf][2*h]   - m);
                    const float p1 = exp2f(Sacc[mf][nf][2*h+1] - m);
                    *reinterpret_cast<__half2*>(
                        &Ps[row * PSH + ni * 16 + nf * 8 + 2 * tg]) =
                        __floats2half2_rn(p0, p1);
                    psum += p0 + p1;
                }
                psum += __shfl_xor_sync(0xffffffffu, psum, 1);
                psum += __shfl_xor_sync(0xffffffffu, psum, 2);
                if (tg == 0) Ssum[row * 4 + ni] = psum;
            }
        }
        __syncthreads();   // S2

        // ---- update m/l, rescale O ----
        #pragma unroll
        for (int mf = 0; mf < 2; mf++) {
            #pragma unroll
            for (int h = 0; h < 2; h++) {
                const int row = mi * 32 + mf * 16 + h * 8 + g;
                float4 s4 = *reinterpret_cast<const float4*>(&Ssum[row * 4]);
                const float f = exp2f(m_loc[mf][h] - mn[mf][h]);
                l_loc[mf][h] = l_loc[mf][h] * f + (s4.x + s4.y + s4.z + s4.w);
                m_loc[mf][h] = mn[mf][h];
                #pragma unroll
                for (int nf = 0; nf < 8; nf++) {
                    Oacc[mf][nf][2*h]   *= f;
                    Oacc[mf][nf][2*h+1] *= f;
                }
            }
        }

        // ---- Stage 2: O += P V (warp: 32 rows x 64 head cols) ----
        {
            const unsigned aP = su32(Ps + (mi * 32 + lr) * PSH + lc);
            const unsigned aV = su32(Vb + lr * QP + nh * 64 + lc);
            #pragma unroll
            for (int kk = 0; kk < 4; kk++) {
                unsigned p0[4], p1[4];
                ldsm_x4(p0, aP + (kk * 16) * 2);
                ldsm_x4(p1, aP + (16 * PSH + kk * 16) * 2);
                #pragma unroll
                for (int j = 0; j < 4; j++) {
                    unsigned vb[4];
                    ldsm_x4t(vb, aV + (kk * 16 * QP + j * 16) * 2);
                    mma16(Oacc[0][2*j],     p0, vb[0], vb[1]);
                    mma16(Oacc[0][2*j + 1], p0, vb[2], vb[3]);
                    mma16(Oacc[1][2*j],     p1, vb[0], vb[1]);
                    mma16(Oacc[1][2*j + 1], p1, vb[2], vb[3]);
                }
            }
        }
    }

    // ---- epilogue: normalize, store fp32 ----
    #pragma unroll
    for (int mf = 0; mf < 2; mf++) {
        const float inv0 = 1.0f / l_loc[mf][0];
        const float inv1 = 1.0f / l_loc[mf][1];
        const size_t r0 = (size_t)(b * TT + qt * 64 + mi * 32 + mf * 16 + g) * HH;
        #pragma unroll
        for (int nf = 0; nf < 8; nf++) {
            const int col = nh * 64 + nf * 8 + 2 * tg;
            float2 v0, v1;
            v0.x = Oacc[mf][nf][0] * inv0;
            v0.y = Oacc[mf][nf][1] * inv0;
            v1.x = Oacc[mf][nf][2] * inv1;
            v1.y = Oacc[mf][nf][3] * inv1;
            *reinterpret_cast<float2*>(&out[r0 + col])           = v0;
            *reinterpret_cast<float2*>(&out[r0 + 8 * HH + col])  = v1;
        }
    }
}

// ---------------------------------------------------------------------------
extern "C" void kernel_launch(void* const* d_in, const int* in_sizes, int n_in,
                              void* d_out, int out_size)
{
    const float* x  = (const float*)d_in[0];
    const float* Wq = (const float*)d_in[1];
    const float* bq = (const float*)d_in[2];
    const float* Wk = (const float*)d_in[3];
    const float* bk = (const float*)d_in[4];
    const float* Wv = (const float*)d_in[5];
    const float* bv = (const float*)d_in[6];
    float* out = (float*)d_out;

    const int proj_smem  = 2 * 128 * XP * 2;                                  // ~68 KB
    const int flash_smem = (64 * QP * 5 + 64 * PSH) * 2 + 512 * 4 + 256;      // ~176 KB

    cudaFuncSetAttribute(proj_kernel,  cudaFuncAttributeMaxDynamicSharedMemorySize, proj_smem);
    cudaFuncSetAttribute(flash_kernel, cudaFuncAttributeMaxDynamicSharedMemorySize, flash_smem);

    proj_kernel<<<dim3(2, 128, 3), 256, proj_smem>>>(x, Wq, bq, Wk, bk, Wv, bv);
    flash_kernel<<<dim3(32, 8), 256, flash_smem>>>(out);
}

// round 5
// speedup vs baseline: 10.0907x; 1.0595x over previous
#include <cuda_runtime.h>
#include <cuda_fp16.h>
#include <math.h>

#define BB 8
#define TT 2048
#define EE 128
#define HH 256
#define BT (BB*TT)

#define QP  264    // halves pitch for K/V/Q-staging smem tiles (row step = +4 banks)
#define XP  136    // halves pitch for proj tiles

// fp16 scratch for projected Q (pre-scaled by log2e/16), K, V
__device__ __half g_Qh[(size_t)BT*HH];
__device__ __half g_Kh[(size_t)BT*HH];
__device__ __half g_Vh[(size_t)BT*HH];

__device__ __forceinline__ unsigned su32(const void* p) {
    return (unsigned)__cvta_generic_to_shared(p);
}
__device__ __forceinline__ void ldsm_x4(unsigned* r, unsigned a) {
    asm volatile("ldmatrix.sync.aligned.m8n8.x4.shared.b16 {%0,%1,%2,%3}, [%4];"
        : "=r"(r[0]), "=r"(r[1]), "=r"(r[2]), "=r"(r[3]) : "r"(a));
}
__device__ __forceinline__ void ldsm_x4t(unsigned* r, unsigned a) {
    asm volatile("ldmatrix.sync.aligned.m8n8.x4.trans.shared.b16 {%0,%1,%2,%3}, [%4];"
        : "=r"(r[0]), "=r"(r[1]), "=r"(r[2]), "=r"(r[3]) : "r"(a));
}
__device__ __forceinline__ void mma16(float* d, const unsigned* a, unsigned b0, unsigned b1) {
    asm volatile("mma.sync.aligned.m16n8k16.row.col.f32.f16.f16.f32 "
        "{%0,%1,%2,%3},{%4,%5,%6,%7},{%8,%9},{%0,%1,%2,%3};"
        : "+f"(d[0]), "+f"(d[1]), "+f"(d[2]), "+f"(d[3])
        : "r"(a[0]), "r"(a[1]), "r"(a[2]), "r"(a[3]), "r"(b0), "r"(b1));
}
__device__ __forceinline__ void cpa16(unsigned d, const void* s) {
    asm volatile("cp.async.cg.shared.global [%0], [%1], 16;" :: "r"(d), "l"(s));
}
#define CP_COMMIT() asm volatile("cp.async.commit_group;")
#define CP_WAIT0()  asm volatile("cp.async.wait_group 0;")

__device__ __forceinline__ float ex2(float x) {
    float y;
    asm("ex2.approx.ftz.f32 %0, %1;" : "=f"(y) : "f"(x));
    return y;
}
__device__ __forceinline__ unsigned h2u(float a, float b) {
    __half2 h = __floats2half2_rn(a, b);
    return *reinterpret_cast<unsigned*>(&h);
}

// ---------------------------------------------------------------------------
// Projection: out[z] = fp16( (x @ W[z] + b[z]) * scale[z] ), tile 128x128,
// z-loop inside the block so the X tile is loaded once.
// ---------------------------------------------------------------------------
__global__ __launch_bounds__(256, 1) void proj_kernel(
    const float* __restrict__ x,
    const float* __restrict__ Wq, const float* __restrict__ bq,
    const float* __restrict__ Wk, const float* __restrict__ bk,
    const float* __restrict__ Wv, const float* __restrict__ bv)
{
    extern __shared__ __half sh[];
    __half* Xh = sh;              // [128][XP]
    __half* Wh = sh + 128 * XP;   // [128 k][XP]

    const int bn = blockIdx.x;    // 0..1
    const int bm = blockIdx.y;    // 0..127
    const int tid = threadIdx.x;

    // X tile [128][128] fp32 -> fp16 smem (once)
    {
        const float* Xg = x + (size_t)bm * 128 * EE;
        #pragma unroll
        for (int i = 0; i < 16; i++) {
            int s = tid + i * 256;
            int r = s >> 5;
            int c4 = (s & 31) * 4;
            float4 v = *reinterpret_cast<const float4*>(&Xg[r * EE + c4]);
            *reinterpret_cast<__half2*>(&Xh[r * XP + c4])     = __floats2half2_rn(v.x, v.y);
            *reinterpret_cast<__half2*>(&Xh[r * XP + c4 + 2]) = __floats2half2_rn(v.z, v.w);
        }
    }

    const int lane = tid & 31;
    const int wid  = tid >> 5;
    const int g    = lane >> 2;
    const int tg   = lane & 3;
    const int mi   = wid & 1;    // rows mi*64
    const int nj   = wid >> 1;   // cols nj*32
    const int lr   = lane & 15;
    const int lc   = (lane >> 4) << 3;

    const unsigned aX = su32(Xh + (mi * 64 + lr) * XP + lc);
    const unsigned aW = su32(Wh + lr * XP + nj * 32 + lc);

    for (int z = 0; z < 3; z++) {
        const float* W    = (z == 0) ? Wq : ((z == 1) ? Wk : Wv);
        const float* bias = (z == 0) ? bq : ((z == 1) ? bk : bv);
        __half* outp      = (z == 0) ? g_Qh : ((z == 1) ? g_Kh : g_Vh);
        const float scale = (z == 0) ? 0.0901679843431555f : 1.0f;  // log2e/16

        __syncthreads();   // prior z done reading Wh
        #pragma unroll
        for (int i = 0; i < 16; i++) {
            int s = tid + i * 256;
            int r = s >> 5;
            int c4 = (s & 31) * 4;
            float4 v = *reinterpret_cast<const float4*>(&W[r * HH + bn * 128 + c4]);
            *reinterpret_cast<__half2*>(&Wh[r * XP + c4])     = __floats2half2_rn(v.x, v.y);
            *reinterpret_cast<__half2*>(&Wh[r * XP + c4 + 2]) = __floats2half2_rn(v.z, v.w);
        }
        __syncthreads();

        float acc[4][4][4];
        #pragma unroll
        for (int mf = 0; mf < 4; mf++)
            #pragma unroll
            for (int nf = 0; nf < 4; nf++)
                #pragma unroll
                for (int c = 0; c < 4; c++) acc[mf][nf][c] = 0.0f;

        #pragma unroll
        for (int kb = 0; kb < 8; kb++) {
            unsigned a[4][4];
            #pragma unroll
            for (int mf = 0; mf < 4; mf++)
                ldsm_x4(a[mf], aX + (mf * 16 * XP + kb * 16) * 2);
            #pragma unroll
            for (int j = 0; j < 2; j++) {
                unsigned wb[4];
                ldsm_x4t(wb, aW + (kb * 16 * XP + j * 16) * 2);
                #pragma unroll
                for (int mf = 0; mf < 4; mf++) {
                    mma16(acc[mf][2 * j],     a[mf], wb[0], wb[1]);
                    mma16(acc[mf][2 * j + 1], a[mf], wb[2], wb[3]);
                }
            }
        }

        #pragma unroll
        for (int nf = 0; nf < 4; nf++) {
            const int col = nj * 32 + nf * 8 + 2 * tg;
            const float b0 = bias[bn * 128 + col];
            const float b1 = bias[bn * 128 + col + 1];
            #pragma unroll
            for (int mf = 0; mf < 4; mf++) {
                const int r0 = bm * 128 + mi * 64 + mf * 16 + g;
                __half2 h0 = __floats2half2_rn((acc[mf][nf][0] + b0) * scale,
                                               (acc[mf][nf][1] + b1) * scale);
                __half2 h1 = __floats2half2_rn((acc[mf][nf][2] + b0) * scale,
                                               (acc[mf][nf][3] + b1) * scale);
                *reinterpret_cast<__half2*>(&outp[(size_t)r0 * HH + bn * 128 + col])       = h0;
                *reinterpret_cast<__half2*>(&outp[(size_t)(r0 + 8) * HH + bn * 128 + col]) = h1;
            }
        }
    }
}

// ---------------------------------------------------------------------------
// Flash attention, FA2 warp-independent: 8 warps x 16 query rows (BM=128).
// Q in registers, P register-resident (C-frag -> A-frag), m/l in registers.
// Only sync: cp.async double buffer for K/V (BN=64). Grid (16, 8) = 1 wave.
// ---------------------------------------------------------------------------
__global__ __launch_bounds__(256, 1) void flash_kernel(float* __restrict__ out)
{
    extern __shared__ __half sh[];
    __half* Ks = sh;                 // 2 x [64][QP] (also Q staging: 128 rows)
    __half* Vs = sh + 2 * 64 * QP;   // 2 x [64][QP]

    const int qt   = blockIdx.x;     // 128-row query tile
    const int b    = blockIdx.y;
    const int tid  = threadIdx.x;
    const int lane = tid & 31;
    const int w    = tid >> 5;
    const int g    = lane >> 2;
    const int tg   = lane & 3;
    const int lr   = lane & 15;
    const int lc   = (lane >> 4) << 3;

    const int qrow = qt * 128 + w * 16;   // warp's first query row (in batch)

    // ---- stage Q tile [128][256] through Ks, ldmatrix into registers ----
    {
        const __half* Qg = g_Qh + (size_t)(b * TT + qt * 128) * HH;
        #pragma unroll
        for (int i = 0; i < 16; i++) {
            int s = tid + i * 256;
            int r = s >> 5;
            int c8 = (s & 31) * 8;
            *reinterpret_cast<float4*>(Ks + r * QP + c8) =
                *reinterpret_cast<const float4*>(Qg + r * HH + c8);
        }
    }
    __syncthreads();
    unsigned Qf[16][4];
    {
        const unsigned aQ = su32(Ks + (w * 16 + lr) * QP + lc);
        #pragma unroll
        for (int kb = 0; kb < 16; kb++) ldsm_x4(Qf[kb], aQ + (kb * 16) * 2);
    }
    __syncthreads();

    // ---- prime K0/V0 ----
    {
        const __half* Kg = g_Kh + (size_t)(b * TT) * HH;
        const __half* Vg = g_Vh + (size_t)(b * TT) * HH;
        #pragma unroll
        for (int i = 0; i < 8; i++) {
            int s = tid + i * 256;
            int r = s >> 5;
            int c8 = (s & 31) * 8;
            cpa16(su32(Ks + r * QP + c8), Kg + r * HH + c8);
            cpa16(su32(Vs + r * QP + c8), Vg + r * HH + c8);
        }
        CP_COMMIT();
    }

    float Oacc[32][4];
    #pragma unroll
    for (int j2 = 0; j2 < 32; j2++)
        #pragma unroll
        for (int c = 0; c < 4; c++) Oacc[j2][c] = 0.0f;
    float m0 = -1.0e30f, m1 = -1.0e30f, l0 = 0.0f, l1 = 0.0f;

    const int ktmax = 2 * qt + 1;
    for (int kt = 0; kt <= ktmax; ++kt) {
        CP_WAIT0();
        __syncthreads();   // tile kt visible; all warps done with buffer (kt+1)&1

        if (kt < ktmax) {
            const __half* Kg = g_Kh + (size_t)(b * TT + (kt + 1) * 64) * HH;
            const __half* Vg = g_Vh + (size_t)(b * TT + (kt + 1) * 64) * HH;
            __half* Kd = Ks + ((kt + 1) & 1) * 64 * QP;
            __half* Vd = Vs + ((kt + 1) & 1) * 64 * QP;
            #pragma unroll
            for (int i = 0; i < 8; i++) {
                int s = tid + i * 256;
                int r = s >> 5;
                int c8 = (s & 31) * 8;
                cpa16(su32(Kd + r * QP + c8), Kg + r * HH + c8);
                cpa16(su32(Vd + r * QP + c8), Vg + r * HH + c8);
            }
            CP_COMMIT();
        }

        if (kt * 64 <= qrow + 15) {   // warp has at least one unmasked element
            const __half* Kb = Ks + (kt & 1) * 64 * QP;
            const __half* Vb = Vs + (kt & 1) * 64 * QP;

            // ---- stage 1: S(16x64) = Q K^T ----
            float S[8][4];
            #pragma unroll
            for (int nf = 0; nf < 8; nf++)
                #pragma unroll
                for (int c = 0; c < 4; c++) S[nf][c] = 0.0f;

            {
                const unsigned aK = su32(Kb + lr * QP + lc);
                #pragma unroll
                for (int kb = 0; kb < 16; kb++) {
                    #pragma unroll
                    for (int j = 0; j < 4; j++) {
                        unsigned bf[4];
                        ldsm_x4(bf, aK + (j * 16 * QP + kb * 16) * 2);
                        mma16(S[2 * j],     Qf[kb], bf[0], bf[2]);
                        mma16(S[2 * j + 1], Qf[kb], bf[1], bf[3]);
                    }
                }
            }

            // ---- causal mask (diagonal tiles only) ----
            if (kt * 64 + 63 > qrow) {
                const int r0 = qrow + g;
                const int r1 = qrow + 8 + g;
                #pragma unroll
                for (int nf = 0; nf < 8; nf++) {
                    const int col = kt * 64 + nf * 8 + 2 * tg;
                    if (col     > r0) S[nf][0] = -1.0e30f;
                    if (col + 1 > r0) S[nf][1] = -1.0e30f;
                    if (col     > r1) S[nf][2] = -1.0e30f;
                    if (col + 1 > r1) S[nf][3] = -1.0e30f;
                }
            }

            // ---- warp-local row max ----
            float mx0 = -1.0e30f, mx1 = -1.0e30f;
            #pragma unroll
            for (int nf = 0; nf < 8; nf++) {
                mx0 = fmaxf(mx0, fmaxf(S[nf][0], S[nf][1]));
                mx1 = fmaxf(mx1, fmaxf(S[nf][2], S[nf][3]));
            }
            mx0 = fmaxf(mx0, __shfl_xor_sync(0xffffffffu, mx0, 1));
            mx0 = fmaxf(mx0, __shfl_xor_sync(0xffffffffu, mx0, 2));
            mx1 = fmaxf(mx1, __shfl_xor_sync(0xffffffffu, mx1, 1));
            mx1 = fmaxf(mx1, __shfl_xor_sync(0xffffffffu, mx1, 2));
            const float mn0 = fmaxf(m0, mx0);
            const float mn1 = fmaxf(m1, mx1);
            const float f0 = ex2(m0 - mn0);
            const float f1 = ex2(m1 - mn1);
            m0 = mn0; m1 = mn1;

            // ---- P = exp2(S - m) directly into A-fragments (registers) ----
            unsigned Pf[4][4];
            float s0 = 0.0f, s1 = 0.0f;
            #pragma unroll
            for (int nf = 0; nf < 8; nf++) {
                const float p0 = ex2(S[nf][0] - mn0);
                const float p1 = ex2(S[nf][1] - mn0);
                const float p2 = ex2(S[nf][2] - mn1);
                const float p3 = ex2(S[nf][3] - mn1);
                s0 += p0 + p1;
                s1 += p2 + p3;
                const int kk = nf >> 1;
                if ((nf & 1) == 0) {
                    Pf[kk][0] = h2u(p0, p1);
                    Pf[kk][1] = h2u(p2, p3);
                } else {
                    Pf[kk][2] = h2u(p0, p1);
                    Pf[kk][3] = h2u(p2, p3);
                }
            }
            s0 += __shfl_xor_sync(0xffffffffu, s0, 1);
            s0 += __shfl_xor_sync(0xffffffffu, s0, 2);
            s1 += __shfl_xor_sync(0xffffffffu, s1, 1);
            s1 += __shfl_xor_sync(0xffffffffu, s1, 2);
            l0 = l0 * f0 + s0;
            l1 = l1 * f1 + s1;

            // ---- rescale O (skip when max unchanged across whole warp) ----
            if (!__all_sync(0xffffffffu, (f0 == 1.0f) && (f1 == 1.0f))) {
                #pragma unroll
                for (int j2 = 0; j2 < 32; j2++) {
                    Oacc[j2][0] *= f0; Oacc[j2][1] *= f0;
                    Oacc[j2][2] *= f1; Oacc[j2][3] *= f1;
                }
            }

            // ---- stage 2: O(16x256) += P V ----
            {
                const unsigned aV = su32(Vb + lr * QP + lc);
                #pragma unroll
                for (int kk = 0; kk < 4; kk++) {
                    #pragma unroll
                    for (int j = 0; j < 16; j++) {
                        unsigned vb[4];
                        ldsm_x4t(vb, aV + (kk * 16 * QP + j * 16) * 2);
                        mma16(Oacc[2 * j],     Pf[kk], vb[0], vb[1]);
                        mma16(Oacc[2 * j + 1], Pf[kk], vb[2], vb[3]);
                    }
                }
            }
        }
    }

    // ---- epilogue ----
    {
        const float inv0 = 1.0f / l0;
        const float inv1 = 1.0f / l1;
        float* op = out + (size_t)(b * TT + qrow) * HH;
        #pragma unroll
        for (int j2 = 0; j2 < 32; j2++) {
            const int col = j2 * 8 + 2 * tg;
            float2 v0, v1;
            v0.x = Oacc[j2][0] * inv0;
            v0.y = Oacc[j2][1] * inv0;
            v1.x = Oacc[j2][2] * inv1;
            v1.y = Oacc[j2][3] * inv1;
            *reinterpret_cast<float2*>(&op[(size_t)g * HH + col])       = v0;
            *reinterpret_cast<float2*>(&op[(size_t)(g + 8) * HH + col]) = v1;
        }
    }
}

// ---------------------------------------------------------------------------
extern "C" void kernel_launch(void* const* d_in, const int* in_sizes, int n_in,
                              void* d_out, int out_size)
{
    const float* x  = (const float*)d_in[0];
    const float* Wq = (const float*)d_in[1];
    const float* bq = (const float*)d_in[2];
    const float* Wk = (const float*)d_in[3];
    const float* bk = (const float*)d_in[4];
    const float* Wv = (const float*)d_in[5];
    const float* bv = (const float*)d_in[6];
    float* out = (float*)d_out;

    const int proj_smem  = 2 * 128 * XP * 2;       // ~68 KB
    const int flash_smem = 4 * 64 * QP * 2;        // 132 KB (K + V double buffers)

    cudaFuncSetAttribute(proj_kernel,  cudaFuncAttributeMaxDynamicSharedMemorySize, proj_smem);
    cudaFuncSetAttribute(flash_kernel, cudaFuncAttributeMaxDynamicSharedMemorySize, flash_smem);

    proj_kernel<<<dim3(2, 128), 256, proj_smem>>>(x, Wq, bq, Wk, bk, Wv, bv);
    flash_kernel<<<dim3(16, 8), 256, flash_smem>>>(out);
}

// round 6
// speedup vs baseline: 13.7745x; 1.3651x over previous
#include <cuda_runtime.h>
#include <cuda_fp16.h>
#include <math.h>

#define BB 8
#define TT 2048
#define EE 128
#define HH 256
#define BT (BB*TT)

#define QP  264    // halves pitch for Q/K/V smem tiles (row step = +4 banks)
#define XP  136    // halves pitch for proj tiles

// fp16 scratch for projected Q (pre-scaled by log2e/16), K, V
__device__ __half g_Qh[(size_t)BT*HH];
__device__ __half g_Kh[(size_t)BT*HH];
__device__ __half g_Vh[(size_t)BT*HH];

// split-KV partials for heavy tiles (qt>=8): [half][tile=b*8+(qt-8)]
__device__ float g_Op[2][64][128*256];
__device__ float g_mp[2][64][128];
__device__ float g_lp[2][64][128];

// LPT schedule: 24 entries per batch, descending iteration count.
// kind: 0=light full-range, 1=heavy half0 (kt 0..qt), 2=heavy half1 (kt qt+1..2qt+1)
__constant__ int c_qt[24]   = {15,15,7,14,14,6,13,13,12,12,5,11,11,10,10,4,9,9,8,8,3,2,1,0};
__constant__ int c_kind[24] = { 1, 2,0, 1, 2,0, 1, 2, 1, 2,0, 1, 2, 1, 2,0,1,2,1,2,0,0,0,0};

__device__ __forceinline__ unsigned su32(const void* p) {
    return (unsigned)__cvta_generic_to_shared(p);
}
__device__ __forceinline__ void ldsm_x4(unsigned* r, unsigned a) {
    asm volatile("ldmatrix.sync.aligned.m8n8.x4.shared.b16 {%0,%1,%2,%3}, [%4];"
        : "=r"(r[0]), "=r"(r[1]), "=r"(r[2]), "=r"(r[3]) : "r"(a));
}
__device__ __forceinline__ void ldsm_x4t(unsigned* r, unsigned a) {
    asm volatile("ldmatrix.sync.aligned.m8n8.x4.trans.shared.b16 {%0,%1,%2,%3}, [%4];"
        : "=r"(r[0]), "=r"(r[1]), "=r"(r[2]), "=r"(r[3]) : "r"(a));
}
__device__ __forceinline__ void mma16(float* d, const unsigned* a, unsigned b0, unsigned b1) {
    asm volatile("mma.sync.aligned.m16n8k16.row.col.f32.f16.f16.f32 "
        "{%0,%1,%2,%3},{%4,%5,%6,%7},{%8,%9},{%0,%1,%2,%3};"
        : "+f"(d[0]), "+f"(d[1]), "+f"(d[2]), "+f"(d[3])
        : "r"(a[0]), "r"(a[1]), "r"(a[2]), "r"(a[3]), "r"(b0), "r"(b1));
}
__device__ __forceinline__ void cpa16(unsigned d, const void* s) {
    asm volatile("cp.async.cg.shared.global [%0], [%1], 16;" :: "r"(d), "l"(s));
}
#define CP_COMMIT() asm volatile("cp.async.commit_group;")
#define CP_WAIT0()  asm volatile("cp.async.wait_group 0;")

__device__ __forceinline__ float ex2(float x) {
    float y;
    asm("ex2.approx.ftz.f32 %0, %1;" : "=f"(y) : "f"(x));
    return y;
}
__device__ __forceinline__ unsigned h2u(float a, float b) {
    __half2 h = __floats2half2_rn(a, b);
    return *reinterpret_cast<unsigned*>(&h);
}

// ---------------------------------------------------------------------------
// Projection: out[z] = fp16( (x @ W[z] + b[z]) * scale[z] ), tile 128x128,
// z-loop inside the block so the X tile is loaded once.
// ---------------------------------------------------------------------------
__global__ __launch_bounds__(256, 1) void proj_kernel(
    const float* __restrict__ x,
    const float* __restrict__ Wq, const float* __restrict__ bq,
    const float* __restrict__ Wk, const float* __restrict__ bk,
    const float* __restrict__ Wv, const float* __restrict__ bv)
{
    extern __shared__ __half sh[];
    __half* Xh = sh;              // [128][XP]
    __half* Wh = sh + 128 * XP;   // [128 k][XP]

    const int bn = blockIdx.x;    // 0..1
    const int bm = blockIdx.y;    // 0..127
    const int tid = threadIdx.x;

    {
        const float* Xg = x + (size_t)bm * 128 * EE;
        #pragma unroll
        for (int i = 0; i < 16; i++) {
            int s = tid + i * 256;
            int r = s >> 5;
            int c4 = (s & 31) * 4;
            float4 v = *reinterpret_cast<const float4*>(&Xg[r * EE + c4]);
            *reinterpret_cast<__half2*>(&Xh[r * XP + c4])     = __floats2half2_rn(v.x, v.y);
            *reinterpret_cast<__half2*>(&Xh[r * XP + c4 + 2]) = __floats2half2_rn(v.z, v.w);
        }
    }

    const int lane = tid & 31;
    const int wid  = tid >> 5;
    const int g    = lane >> 2;
    const int tg   = lane & 3;
    const int mi   = wid & 1;
    const int nj   = wid >> 1;
    const int lr   = lane & 15;
    const int lc   = (lane >> 4) << 3;

    const unsigned aX = su32(Xh + (mi * 64 + lr) * XP + lc);
    const unsigned aW = su32(Wh + lr * XP + nj * 32 + lc);

    for (int z = 0; z < 3; z++) {
        const float* W    = (z == 0) ? Wq : ((z == 1) ? Wk : Wv);
        const float* bias = (z == 0) ? bq : ((z == 1) ? bk : bv);
        __half* outp      = (z == 0) ? g_Qh : ((z == 1) ? g_Kh : g_Vh);
        const float scale = (z == 0) ? 0.0901679843431555f : 1.0f;  // log2e/16

        __syncthreads();
        #pragma unroll
        for (int i = 0; i < 16; i++) {
            int s = tid + i * 256;
            int r = s >> 5;
            int c4 = (s & 31) * 4;
            float4 v = *reinterpret_cast<const float4*>(&W[r * HH + bn * 128 + c4]);
            *reinterpret_cast<__half2*>(&Wh[r * XP + c4])     = __floats2half2_rn(v.x, v.y);
            *reinterpret_cast<__half2*>(&Wh[r * XP + c4 + 2]) = __floats2half2_rn(v.z, v.w);
        }
        __syncthreads();

        float acc[4][4][4];
        #pragma unroll
        for (int mf = 0; mf < 4; mf++)
            #pragma unroll
            for (int nf = 0; nf < 4; nf++)
                #pragma unroll
                for (int c = 0; c < 4; c++) acc[mf][nf][c] = 0.0f;

        #pragma unroll
        for (int kb = 0; kb < 8; kb++) {
            unsigned a[4][4];
            #pragma unroll
            for (int mf = 0; mf < 4; mf++)
                ldsm_x4(a[mf], aX + (mf * 16 * XP + kb * 16) * 2);
            #pragma unroll
            for (int j = 0; j < 2; j++) {
                unsigned wb[4];
                ldsm_x4t(wb, aW + (kb * 16 * XP + j * 16) * 2);
                #pragma unroll
                for (int mf = 0; mf < 4; mf++) {
                    mma16(acc[mf][2 * j],     a[mf], wb[0], wb[1]);
                    mma16(acc[mf][2 * j + 1], a[mf], wb[2], wb[3]);
                }
            }
        }

        #pragma unroll
        for (int nf = 0; nf < 4; nf++) {
            const int col = nj * 32 + nf * 8 + 2 * tg;
            const float b0 = bias[bn * 128 + col];
            const float b1 = bias[bn * 128 + col + 1];
            #pragma unroll
            for (int mf = 0; mf < 4; mf++) {
                const int r0 = bm * 128 + mi * 64 + mf * 16 + g;
                __half2 h0 = __floats2half2_rn((acc[mf][nf][0] + b0) * scale,
                                               (acc[mf][nf][1] + b1) * scale);
                __half2 h1 = __floats2half2_rn((acc[mf][nf][2] + b0) * scale,
                                               (acc[mf][nf][3] + b1) * scale);
                *reinterpret_cast<__half2*>(&outp[(size_t)r0 * HH + bn * 128 + col])       = h0;
                *reinterpret_cast<__half2*>(&outp[(size_t)(r0 + 8) * HH + bn * 128 + col]) = h1;
            }
        }
    }
}

// ---------------------------------------------------------------------------
// Flash attention, FA2 + split-KV. 8 warps x 16 query rows (BM=128).
// Q in smem (no reg spill), P register-resident, m/l in registers.
// Block = (batch, schedule idx) -> (qt, kt range, partial-or-final).
// ---------------------------------------------------------------------------
__global__ __launch_bounds__(256, 1) void flash_kernel(float* __restrict__ out)
{
    extern __shared__ __half sh[];
    __half* Qsm = sh;                     // [128][QP]
    __half* Ks  = sh + 128 * QP;          // 2 x [64][QP]
    __half* Vs  = Ks + 2 * 64 * QP;       // 2 x [64][QP]

    const int b    = blockIdx.x;
    const int idx  = blockIdx.y;
    const int qt   = c_qt[idx];
    const int kind = c_kind[idx];
    const int kt_begin = (kind == 2) ? qt + 1 : 0;
    const int kt_end   = (kind == 1) ? qt : 2 * qt + 1;

    const int tid  = threadIdx.x;
    const int lane = tid & 31;
    const int w    = tid >> 5;
    const int g    = lane >> 2;
    const int tg   = lane & 3;
    const int lr   = lane & 15;
    const int lc   = (lane >> 4) << 3;

    const int qrow = qt * 128 + w * 16;   // warp's first query row (in batch)

    // ---- prime Q + K(kt_begin)/V(kt_begin) via cp.async ----
    {
        const __half* Qg = g_Qh + (size_t)(b * TT + qt * 128) * HH;
        const __half* Kg = g_Kh + (size_t)(b * TT + kt_begin * 64) * HH;
        const __half* Vg = g_Vh + (size_t)(b * TT + kt_begin * 64) * HH;
        __half* Kd = Ks + (kt_begin & 1) * 64 * QP;
        __half* Vd = Vs + (kt_begin & 1) * 64 * QP;
        #pragma unroll
        for (int i = 0; i < 16; i++) {
            int s = tid + i * 256;
            int r = s >> 5;
            int c8 = (s & 31) * 8;
            cpa16(su32(Qsm + r * QP + c8), Qg + r * HH + c8);
        }
        #pragma unroll
        for (int i = 0; i < 8; i++) {
            int s = tid + i * 256;
            int r = s >> 5;
            int c8 = (s & 31) * 8;
            cpa16(su32(Kd + r * QP + c8), Kg + r * HH + c8);
            cpa16(su32(Vd + r * QP + c8), Vg + r * HH + c8);
        }
        CP_COMMIT();
    }

    float Oacc[32][4];
    #pragma unroll
    for (int j2 = 0; j2 < 32; j2++)
        #pragma unroll
        for (int c = 0; c < 4; c++) Oacc[j2][c] = 0.0f;
    float m0 = -1.0e30f, m1 = -1.0e30f, l0 = 0.0f, l1 = 0.0f;

    const unsigned aQ = su32(Qsm + (w * 16 + lr) * QP + lc);

    for (int kt = kt_begin; kt <= kt_end; ++kt) {
        CP_WAIT0();
        __syncthreads();

        if (kt < kt_end) {
            const __half* Kg = g_Kh + (size_t)(b * TT + (kt + 1) * 64) * HH;
            const __half* Vg = g_Vh + (size_t)(b * TT + (kt + 1) * 64) * HH;
            __half* Kd = Ks + ((kt + 1) & 1) * 64 * QP;
            __half* Vd = Vs + ((kt + 1) & 1) * 64 * QP;
            #pragma unroll
            for (int i = 0; i < 8; i++) {
                int s = tid + i * 256;
                int r = s >> 5;
                int c8 = (s & 31) * 8;
                cpa16(su32(Kd + r * QP + c8), Kg + r * HH + c8);
                cpa16(su32(Vd + r * QP + c8), Vg + r * HH + c8);
            }
            CP_COMMIT();
        }

        if (kt * 64 <= qrow + 15) {   // warp has >=1 unmasked element
            const __half* Kb = Ks + (kt & 1) * 64 * QP;
            const __half* Vb = Vs + (kt & 1) * 64 * QP;

            // ---- stage 1: S(16x64) = Q K^T ----
            float S[8][4];
            #pragma unroll
            for (int nf = 0; nf < 8; nf++)
                #pragma unroll
                for (int c = 0; c < 4; c++) S[nf][c] = 0.0f;

            {
                const unsigned aK = su32(Kb + lr * QP + lc);
                #pragma unroll
                for (int kb = 0; kb < 16; kb++) {
                    unsigned qf[4];
                    ldsm_x4(qf, aQ + (kb * 16) * 2);
                    #pragma unroll
                    for (int j = 0; j < 4; j++) {
                        unsigned bf[4];
                        ldsm_x4(bf, aK + (j * 16 * QP + kb * 16) * 2);
                        mma16(S[2 * j],     qf, bf[0], bf[2]);
                        mma16(S[2 * j + 1], qf, bf[1], bf[3]);
                    }
                }
            }

            // ---- causal mask (diagonal tiles only) ----
            if (kt * 64 + 63 > qrow) {
                const int r0 = qrow + g;
                const int r1 = qrow + 8 + g;
                #pragma unroll
                for (int nf = 0; nf < 8; nf++) {
                    const int col = kt * 64 + nf * 8 + 2 * tg;
                    if (col     > r0) S[nf][0] = -1.0e30f;
                    if (col + 1 > r0) S[nf][1] = -1.0e30f;
                    if (col     > r1) S[nf][2] = -1.0e30f;
                    if (col + 1 > r1) S[nf][3] = -1.0e30f;
                }
            }

            // ---- warp-local row max ----
            float mx0 = -1.0e30f, mx1 = -1.0e30f;
            #pragma unroll
            for (int nf = 0; nf < 8; nf++) {
                mx0 = fmaxf(mx0, fmaxf(S[nf][0], S[nf][1]));
                mx1 = fmaxf(mx1, fmaxf(S[nf][2], S[nf][3]));
            }
            mx0 = fmaxf(mx0, __shfl_xor_sync(0xffffffffu, mx0, 1));
            mx0 = fmaxf(mx0, __shfl_xor_sync(0xffffffffu, mx0, 2));
            mx1 = fmaxf(mx1, __shfl_xor_sync(0xffffffffu, mx1, 1));
            mx1 = fmaxf(mx1, __shfl_xor_sync(0xffffffffu, mx1, 2));
            const float mn0 = fmaxf(m0, mx0);
            const float mn1 = fmaxf(m1, mx1);
            const float f0 = ex2(m0 - mn0);
            const float f1 = ex2(m1 - mn1);
            m0 = mn0; m1 = mn1;

            // ---- P = exp2(S - m) into A-fragments (registers) ----
            unsigned Pf[4][4];
            float s0 = 0.0f, s1 = 0.0f;
            #pragma unroll
            for (int nf = 0; nf < 8; nf++) {
                const float p0 = ex2(S[nf][0] - mn0);
                const float p1 = ex2(S[nf][1] - mn0);
                const float p2 = ex2(S[nf][2] - mn1);
                const float p3 = ex2(S[nf][3] - mn1);
                s0 += p0 + p1;
                s1 += p2 + p3;
                const int kk = nf >> 1;
                if ((nf & 1) == 0) {
                    Pf[kk][0] = h2u(p0, p1);
                    Pf[kk][1] = h2u(p2, p3);
                } else {
                    Pf[kk][2] = h2u(p0, p1);
                    Pf[kk][3] = h2u(p2, p3);
                }
            }
            s0 += __shfl_xor_sync(0xffffffffu, s0, 1);
            s0 += __shfl_xor_sync(0xffffffffu, s0, 2);
            s1 += __shfl_xor_sync(0xffffffffu, s1, 1);
            s1 += __shfl_xor_sync(0xffffffffu, s1, 2);
            l0 = l0 * f0 + s0;
            l1 = l1 * f1 + s1;

            // ---- rescale O (skip when max unchanged across whole warp) ----
            if (!__all_sync(0xffffffffu, (f0 == 1.0f) && (f1 == 1.0f))) {
                #pragma unroll
                for (int j2 = 0; j2 < 32; j2++) {
                    Oacc[j2][0] *= f0; Oacc[j2][1] *= f0;
                    Oacc[j2][2] *= f1; Oacc[j2][3] *= f1;
                }
            }

            // ---- stage 2: O(16x256) += P V ----
            {
                const unsigned aV = su32(Vb + lr * QP + lc);
                #pragma unroll
                for (int kk = 0; kk < 4; kk++) {
                    #pragma unroll
                    for (int j = 0; j < 16; j++) {
                        unsigned vb[4];
                        ldsm_x4t(vb, aV + (kk * 16 * QP + j * 16) * 2);
                        mma16(Oacc[2 * j],     Pf[kk], vb[0], vb[1]);
                        mma16(Oacc[2 * j + 1], Pf[kk], vb[2], vb[3]);
                    }
                }
            }
        }
    }

    // ---- epilogue ----
    if (kind == 0) {
        const float inv0 = 1.0f / l0;
        const float inv1 = 1.0f / l1;
        float* op = out + (size_t)(b * TT + qrow) * HH;
        #pragma unroll
        for (int j2 = 0; j2 < 32; j2++) {
            const int col = j2 * 8 + 2 * tg;
            float2 v0, v1;
            v0.x = Oacc[j2][0] * inv0;
            v0.y = Oacc[j2][1] * inv0;
            v1.x = Oacc[j2][2] * inv1;
            v1.y = Oacc[j2][3] * inv1;
            *reinterpret_cast<float2*>(&op[(size_t)g * HH + col])       = v0;
            *reinterpret_cast<float2*>(&op[(size_t)(g + 8) * HH + col]) = v1;
        }
    } else {
        const int half = kind - 1;
        const int ht   = b * 8 + (qt - 8);
        float* op = &g_Op[half][ht][(w * 16) * 256];
        #pragma unroll
        for (int j2 = 0; j2 < 32; j2++) {
            const int col = j2 * 8 + 2 * tg;
            float2 v0, v1;
            v0.x = Oacc[j2][0]; v0.y = Oacc[j2][1];
            v1.x = Oacc[j2][2]; v1.y = Oacc[j2][3];
            *reinterpret_cast<float2*>(&op[g * 256 + col])       = v0;
            *reinterpret_cast<float2*>(&op[(g + 8) * 256 + col]) = v1;
        }
        if (tg == 0) {
            g_mp[half][ht][w * 16 + g]     = m0;
            g_lp[half][ht][w * 16 + g]     = l0;
            g_mp[half][ht][w * 16 + 8 + g] = m1;
            g_lp[half][ht][w * 16 + 8 + g] = l1;
        }
    }
}

// ---------------------------------------------------------------------------
// Combine: merge the two split-KV partials of each heavy tile.
// grid (128 rows, 64 tiles), block 256 (one col each).
// ---------------------------------------------------------------------------
__global__ __launch_bounds__(256, 1) void combine_kernel(float* __restrict__ out)
{
    const int row  = blockIdx.x;   // 0..127
    const int tile = blockIdx.y;   // 0..63
    const int c    = threadIdx.x;  // 0..255
    const int b    = tile >> 3;
    const int qt   = 8 + (tile & 7);

    const float m1v = g_mp[0][tile][row];
    const float m2v = g_mp[1][tile][row];
    const float l1v = g_lp[0][tile][row];
    const float l2v = g_lp[1][tile][row];
    const float m = fmaxf(m1v, m2v);
    const float w1 = ex2(m1v - m);
    const float w2 = ex2(m2v - m);
    const float inv = 1.0f / (w1 * l1v + w2 * l2v);

    const float o1 = g_Op[0][tile][row * 256 + c];
    const float o2 = g_Op[1][tile][row * 256 + c];
    out[((size_t)(b * TT + qt * 128 + row)) * HH + c] = (w1 * o1 + w2 * o2) * inv;
}

// ---------------------------------------------------------------------------
extern "C" void kernel_launch(void* const* d_in, const int* in_sizes, int n_in,
                              void* d_out, int out_size)
{
    const float* x  = (const float*)d_in[0];
    const float* Wq = (const float*)d_in[1];
    const float* bq = (const float*)d_in[2];
    const float* Wk = (const float*)d_in[3];
    const float* bk = (const float*)d_in[4];
    const float* Wv = (const float*)d_in[5];
    const float* bv = (const float*)d_in[6];
    float* out = (float*)d_out;

    const int proj_smem  = 2 * 128 * XP * 2;                    // ~68 KB
    const int flash_smem = (128 * QP + 4 * 64 * QP) * 2;        // ~198 KB

    cudaFuncSetAttribute(proj_kernel,  cudaFuncAttributeMaxDynamicSharedMemorySize, proj_smem);
    cudaFuncSetAttribute(flash_kernel, cudaFuncAttributeMaxDynamicSharedMemorySize, flash_smem);

    proj_kernel<<<dim3(2, 128), 256, proj_smem>>>(x, Wq, bq, Wk, bk, Wv, bv);
    flash_kernel<<<dim3(8, 24), 256, flash_smem>>>(out);
    combine_kernel<<<dim3(128, 64), 256>>>(out);
}

// round 11
// speedup vs baseline: 14.5455x; 1.0560x over previous
#include <cuda_runtime.h>
#include <cuda_fp16.h>
#include <math.h>
#include <stdint.h>

#define BB 8
#define TT 2048
#define EE 128
#define HH 256
#define BT (BB*TT)

#define QP  264    // halves pitch for Q/K/V smem tiles (row step = +4 banks)
#define XP  136    // halves pitch for proj tiles

// fp16 scratch for projected Q (pre-scaled by log2e/16), K, V
__device__ __half g_Qh[(size_t)BT*HH];
__device__ __half g_Kh[(size_t)BT*HH];
__device__ __half g_Vh[(size_t)BT*HH];

// split-KV partials (no-max softmax -> only O and l needed)
__device__ float g_Op[2][64][128*256];
__device__ float g_lp[2][64][128];

// LPT schedule: kind 0=light full, 1=heavy half0 (0..qt), 2=heavy half1 (qt+1..2qt+1)
__constant__ int c_qt[24]   = {15,15,7,14,14,6,13,13,12,12,5,11,11,10,10,4,9,9,8,8,3,2,1,0};
__constant__ int c_kind[24] = { 1, 2,0, 1, 2,0, 1, 2, 1, 2,0, 1, 2, 1, 2,0,1,2,1,2,0,0,0,0};

__device__ __forceinline__ unsigned su32(const void* p) {
    return (unsigned)__cvta_generic_to_shared(p);
}
__device__ __forceinline__ void ldsm_x4(unsigned* r, unsigned a) {
    asm volatile("ldmatrix.sync.aligned.m8n8.x4.shared.b16 {%0,%1,%2,%3}, [%4];"
        : "=r"(r[0]), "=r"(r[1]), "=r"(r[2]), "=r"(r[3]) : "r"(a));
}
__device__ __forceinline__ void ldsm_x4t(unsigned* r, unsigned a) {
    asm volatile("ldmatrix.sync.aligned.m8n8.x4.trans.shared.b16 {%0,%1,%2,%3}, [%4];"
        : "=r"(r[0]), "=r"(r[1]), "=r"(r[2]), "=r"(r[3]) : "r"(a));
}
__device__ __forceinline__ void mma16(float* d, const unsigned* a, unsigned b0, unsigned b1) {
    asm volatile("mma.sync.aligned.m16n8k16.row.col.f32.f16.f16.f32 "
        "{%0,%1,%2,%3},{%4,%5,%6,%7},{%8,%9},{%0,%1,%2,%3};"
        : "+f"(d[0]), "+f"(d[1]), "+f"(d[2]), "+f"(d[3])
        : "r"(a[0]), "r"(a[1]), "r"(a[2]), "r"(a[3]), "r"(b0), "r"(b1));
}
__device__ __forceinline__ void cpa16(unsigned d, const void* s) {
    asm volatile("cp.async.cg.shared.global [%0], [%1], 16;" :: "r"(d), "l"(s));
}
#define CP_COMMIT() asm volatile("cp.async.commit_group;")
#define CP_WAIT0()  asm volatile("cp.async.wait_group 0;")
#define CP_WAIT1()  asm volatile("cp.async.wait_group 1;")

__device__ __forceinline__ float ex2(float x) {
    float y; asm("ex2.approx.ftz.f32 %0, %1;" : "=f"(y) : "f"(x)); return y;
}
__device__ __forceinline__ unsigned h2u(float a, float b) {
    __half2 h = __floats2half2_rn(a, b);
    return *reinterpret_cast<unsigned*>(&h);
}

// S(16x64) = Q(16x256) K(64x256)^T for one warp. aQ/aK are per-warp ldsm bases.
__device__ __forceinline__ void compute_S(float S[8][4], unsigned aQ, unsigned aK) {
    #pragma unroll
    for (int nf = 0; nf < 8; nf++)
        #pragma unroll
        for (int c = 0; c < 4; c++) S[nf][c] = 0.0f;
    #pragma unroll
    for (int kb = 0; kb < 16; kb++) {
        unsigned qf[4];
        ldsm_x4(qf, aQ + kb * 32);
        #pragma unroll
        for (int j = 0; j < 4; j++) {
            unsigned bf[4];
            ldsm_x4(bf, aK + (j * 16 * QP + kb * 16) * 2);
            mma16(S[2 * j],     qf, bf[0], bf[2]);
            mma16(S[2 * j + 1], qf, bf[1], bf[3]);
        }
    }
}

// ---------------------------------------------------------------------------
// Projection: out[z] = fp16( (x @ W[z] + b[z]) * scale[z] ), tile 128x128,
// z-loop inside the block reusing the X tile. 2 blocks/SM.
// ---------------------------------------------------------------------------
__global__ __launch_bounds__(256, 2) void proj_kernel(
    const float* __restrict__ x,
    const float* __restrict__ Wq, const float* __restrict__ bq,
    const float* __restrict__ Wk, const float* __restrict__ bk,
    const float* __restrict__ Wv, const float* __restrict__ bv)
{
    extern __shared__ __half sh[];
    __half* Xh = sh;              // [128][XP]
    __half* Wh = sh + 128 * XP;   // [128 k][XP]

    const int bn = blockIdx.x;    // 0..1
    const int bm = blockIdx.y;    // 0..127
    const int tid = threadIdx.x;

    {
        const float* Xg = x + (size_t)bm * 128 * EE;
        #pragma unroll
        for (int i = 0; i < 16; i++) {
            int s = tid + i * 256;
            int r = s >> 5;
            int c4 = (s & 31) * 4;
            float4 v = *reinterpret_cast<const float4*>(&Xg[r * EE + c4]);
            *reinterpret_cast<__half2*>(&Xh[r * XP + c4])     = __floats2half2_rn(v.x, v.y);
            *reinterpret_cast<__half2*>(&Xh[r * XP + c4 + 2]) = __floats2half2_rn(v.z, v.w);
        }
    }

    const int lane = tid & 31;
    const int wid  = tid >> 5;
    const int g    = lane >> 2;
    const int tg   = lane & 3;
    const int mi   = wid & 1;
    const int nj   = wid >> 1;
    const int lr   = lane & 15;
    const int lc   = (lane >> 4) << 3;

    const unsigned aX = su32(Xh + (mi * 64 + lr) * XP + lc);
    const unsigned aW = su32(Wh + lr * XP + nj * 32 + lc);

    for (int z = 0; z < 3; z++) {
        const float* W    = (z == 0) ? Wq : ((z == 1) ? Wk : Wv);
        const float* bias = (z == 0) ? bq : ((z == 1) ? bk : bv);
        __half* outp      = (z == 0) ? g_Qh : ((z == 1) ? g_Kh : g_Vh);
        const float scale = (z == 0) ? 0.0901679843431555f : 1.0f;  // log2e/16

        __syncthreads();
        #pragma unroll
        for (int i = 0; i < 16; i++) {
            int s = tid + i * 256;
            int r = s >> 5;
            int c4 = (s & 31) * 4;
            float4 v = *reinterpret_cast<const float4*>(&W[r * HH + bn * 128 + c4]);
            *reinterpret_cast<__half2*>(&Wh[r * XP + c4])     = __floats2half2_rn(v.x, v.y);
            *reinterpret_cast<__half2*>(&Wh[r * XP + c4 + 2]) = __floats2half2_rn(v.z, v.w);
        }
        __syncthreads();

        float acc[4][4][4];
        #pragma unroll
        for (int mf = 0; mf < 4; mf++)
            #pragma unroll
            for (int nf = 0; nf < 4; nf++)
                #pragma unroll
                for (int c = 0; c < 4; c++) acc[mf][nf][c] = 0.0f;

        #pragma unroll
        for (int kb = 0; kb < 8; kb++) {
            unsigned a[4][4];
            #pragma unroll
            for (int mf = 0; mf < 4; mf++)
                ldsm_x4(a[mf], aX + (mf * 16 * XP + kb * 16) * 2);
            #pragma unroll
            for (int j = 0; j < 2; j++) {
                unsigned wb[4];
                ldsm_x4t(wb, aW + (kb * 16 * XP + j * 16) * 2);
                #pragma unroll
                for (int mf = 0; mf < 4; mf++) {
                    mma16(acc[mf][2 * j],     a[mf], wb[0], wb[1]);
                    mma16(acc[mf][2 * j + 1], a[mf], wb[2], wb[3]);
                }
            }
        }

        #pragma unroll
        for (int nf = 0; nf < 4; nf++) {
            const int col = nj * 32 + nf * 8 + 2 * tg;
            const float b0 = bias[bn * 128 + col];
            const float b1 = bias[bn * 128 + col + 1];
            #pragma unroll
            for (int mf = 0; mf < 4; mf++) {
                const int r0 = bm * 128 + mi * 64 + mf * 16 + g;
                __half2 h0 = __floats2half2_rn((acc[mf][nf][0] + b0) * scale,
                                               (acc[mf][nf][1] + b1) * scale);
                __half2 h1 = __floats2half2_rn((acc[mf][nf][2] + b0) * scale,
                                               (acc[mf][nf][3] + b1) * scale);
                *reinterpret_cast<__half2*>(&outp[(size_t)r0 * HH + bn * 128 + col])       = h0;
                *reinterpret_cast<__half2*>(&outp[(size_t)(r0 + 8) * HH + bn * 128 + col]) = h1;
            }
        }
    }
}

// ---------------------------------------------------------------------------
// Flash attention, FA2 + split-KV + no-max softmax + cross-tile S pipelining.
// 8 warps x 16 query rows (BM=128). Per iter: softmax(S_kt) ->
// [compute_S(kt+1) || stage2(kt)] as independent tensor streams.
// ---------------------------------------------------------------------------
__global__ __launch_bounds__(256, 1) void flash_kernel(float* __restrict__ out)
{
    extern __shared__ __half sh[];
    __half* Qsm = sh;                     // [128][QP]
    __half* Ks  = sh + 128 * QP;          // 2 x [64][QP]
    __half* Vs  = Ks + 2 * 64 * QP;       // 2 x [64][QP]

    const int b    = blockIdx.x;
    const int idx  = blockIdx.y;
    const int qt   = c_qt[idx];
    const int kind = c_kind[idx];
    const int kt_begin = (kind == 2) ? qt + 1 : 0;
    const int kt_end   = (kind == 1) ? qt : 2 * qt + 1;   // every range has >= 2 tiles

    const int tid  = threadIdx.x;
    const int lane = tid & 31;
    const int w    = tid >> 5;
    const int g    = lane >> 2;
    const int tg   = lane & 3;
    const int lr   = lane & 15;
    const int lc   = (lane >> 4) << 3;

    const int qrow = qt * 128 + w * 16;

    // ---- prologue: group0 = Q + KV(kt_begin), group1 = KV(kt_begin+1) ----
    {
        const __half* Qg = g_Qh + (size_t)(b * TT + qt * 128) * HH;
        const __half* Kg = g_Kh + (size_t)(b * TT + kt_begin * 64) * HH;
        const __half* Vg = g_Vh + (size_t)(b * TT + kt_begin * 64) * HH;
        __half* Kd = Ks + (kt_begin & 1) * 64 * QP;
        __half* Vd = Vs + (kt_begin & 1) * 64 * QP;
        #pragma unroll
        for (int i = 0; i < 16; i++) {
            int s = tid + i * 256;
            int r = s >> 5;
            int c8 = (s & 31) * 8;
            cpa16(su32(Qsm + r * QP + c8), Qg + r * HH + c8);
        }
        #pragma unroll
        for (int i = 0; i < 8; i++) {
            int s = tid + i * 256;
            int r = s >> 5;
            int c8 = (s & 31) * 8;
            cpa16(su32(Kd + r * QP + c8), Kg + r * HH + c8);
            cpa16(su32(Vd + r * QP + c8), Vg + r * HH + c8);
        }
        CP_COMMIT();

        const int k1 = kt_begin + 1;
        const __half* Kg1 = g_Kh + (size_t)(b * TT + k1 * 64) * HH;
        const __half* Vg1 = g_Vh + (size_t)(b * TT + k1 * 64) * HH;
        __half* Kd1 = Ks + (k1 & 1) * 64 * QP;
        __half* Vd1 = Vs + (k1 & 1) * 64 * QP;
        #pragma unroll
        for (int i = 0; i < 8; i++) {
            int s = tid + i * 256;
            int r = s >> 5;
            int c8 = (s & 31) * 8;
            cpa16(su32(Kd1 + r * QP + c8), Kg1 + r * HH + c8);
            cpa16(su32(Vd1 + r * QP + c8), Vg1 + r * HH + c8);
        }
        CP_COMMIT();
    }
    CP_WAIT1();         // Q + KV(kt_begin) resident; KV(kt_begin+1) in flight
    __syncthreads();

    const unsigned aQ  = su32(Qsm + (w * 16 + lr) * QP + lc);
    const unsigned aK0 = su32(Ks + lr * QP + lc);
    const unsigned aK1 = aK0 + 64 * QP * 2;
    const unsigned aV0 = su32(Vs + lr * QP + lc);
    const unsigned aV1 = aV0 + 64 * QP * 2;

    float S[8][4];
    compute_S(S, aQ, (kt_begin & 1) ? aK1 : aK0);   // kt_begin active for every warp

    float Oacc[32][4];
    #pragma unroll
    for (int j2 = 0; j2 < 32; j2++)
        #pragma unroll
        for (int c = 0; c < 4; c++) Oacc[j2][c] = 0.0f;
    float l0 = 0.0f, l1 = 0.0f;

    for (int kt = kt_begin; kt <= kt_end; ++kt) {
        const bool act = (kt * 64 <= qrow + 15);

        // ---- softmax: P = exp2(S), masked; l accumulates per-thread ----
        unsigned Pf[4][4];
        if (act) {
            const bool nm = (kt * 64 + 63 > qrow);
            const int r0 = qrow + g;
            const int r1 = qrow + 8 + g;
            #pragma unroll
            for (int nf = 0; nf < 8; nf++) {
                float p0 = ex2(S[nf][0]);
                float p1 = ex2(S[nf][1]);
                float p2 = ex2(S[nf][2]);
                float p3 = ex2(S[nf][3]);
                if (nm) {
                    const int col = kt * 64 + nf * 8 + 2 * tg;
                    if (col     > r0) p0 = 0.0f;
                    if (col + 1 > r0) p1 = 0.0f;
                    if (col     > r1) p2 = 0.0f;
                    if (col + 1 > r1) p3 = 0.0f;
                }
                l0 += p0 + p1;
                l1 += p2 + p3;
                const int kk = nf >> 1;
                if ((nf & 1) == 0) {
                    Pf[kk][0] = h2u(p0, p1);
                    Pf[kk][1] = h2u(p2, p3);
                } else {
                    Pf[kk][2] = h2u(p0, p1);
                    Pf[kk][3] = h2u(p2, p3);
                }
            }
        }

        const bool have_next = (kt < kt_end);
        if (have_next) {
            CP_WAIT0();          // KV(kt+1) resident
            __syncthreads();
            if ((kt + 1) * 64 <= qrow + 15)
                compute_S(S, aQ, ((kt + 1) & 1) ? aK1 : aK0);   // next tile's S
        }

        // ---- stage2: O += P V(kt) (independent of compute_S above) ----
        if (act) {
            const unsigned aV = (kt & 1) ? aV1 : aV0;
            #pragma unroll
            for (int kk = 0; kk < 4; kk++) {
                #pragma unroll
                for (int j = 0; j < 16; j++) {
                    unsigned vb[4];
                    ldsm_x4t(vb, aV + (kk * 16 * QP + j * 16) * 2);
                    mma16(Oacc[2 * j],     Pf[kk], vb[0], vb[1]);
                    mma16(Oacc[2 * j + 1], Pf[kk], vb[2], vb[3]);
                }
            }
        }

        // ---- prefetch KV(kt+2) into buffer (kt&1) after all reads done ----
        if (kt + 2 <= kt_end) {
            __syncthreads();
            const __half* Kg = g_Kh + (size_t)(b * TT + (kt + 2) * 64) * HH;
            const __half* Vg = g_Vh + (size_t)(b * TT + (kt + 2) * 64) * HH;
            __half* Kd = Ks + (kt & 1) * 64 * QP;
            __half* Vd = Vs + (kt & 1) * 64 * QP;
            #pragma unroll
            for (int i = 0; i < 8; i++) {
                int s = tid + i * 256;
                int r = s >> 5;
                int c8 = (s & 31) * 8;
                cpa16(su32(Kd + r * QP + c8), Kg + r * HH + c8);
                cpa16(su32(Vd + r * QP + c8), Vg + r * HH + c8);
            }
            CP_COMMIT();
        }
    }

    // ---- epilogue: reduce l across the 4 tg lanes, normalize/store ----
    l0 += __shfl_xor_sync(0xffffffffu, l0, 1);
    l0 += __shfl_xor_sync(0xffffffffu, l0, 2);
    l1 += __shfl_xor_sync(0xffffffffu, l1, 1);
    l1 += __shfl_xor_sync(0xffffffffu, l1, 2);

    if (kind == 0) {
        const float inv0 = 1.0f / l0;
        const float inv1 = 1.0f / l1;
        float* op = out + (size_t)(b * TT + qrow) * HH;
        #pragma unroll
        for (int j2 = 0; j2 < 32; j2++) {
            const int col = j2 * 8 + 2 * tg;
            float2 v0, v1;
            v0.x = Oacc[j2][0] * inv0;
            v0.y = Oacc[j2][1] * inv0;
            v1.x = Oacc[j2][2] * inv1;
            v1.y = Oacc[j2][3] * inv1;
            *reinterpret_cast<float2*>(&op[(size_t)g * HH + col])       = v0;
            *reinterpret_cast<float2*>(&op[(size_t)(g + 8) * HH + col]) = v1;
        }
    } else {
        const int half = kind - 1;
        const int ht   = b * 8 + (qt - 8);
        float* op = &g_Op[half][ht][(w * 16) * 256];
        #pragma unroll
        for (int j2 = 0; j2 < 32; j2++) {
            const int col = j2 * 8 + 2 * tg;
            float2 v0, v1;
            v0.x = Oacc[j2][0]; v0.y = Oacc[j2][1];
            v1.x = Oacc[j2][2]; v1.y = Oacc[j2][3];
            *reinterpret_cast<float2*>(&op[g * 256 + col])       = v0;
            *reinterpret_cast<float2*>(&op[(g + 8) * 256 + col]) = v1;
        }
        if (tg == 0) {
            g_lp[half][ht][w * 16 + g]     = l0;
            g_lp[half][ht][w * 16 + 8 + g] = l1;
        }
    }
}

// ---------------------------------------------------------------------------
// Combine split-KV partials: out = (o1 + o2) / (l1 + l2).
// ---------------------------------------------------------------------------
__global__ __launch_bounds__(256, 1) void combine_kernel(float* __restrict__ out)
{
    const int row  = blockIdx.x;   // 0..127
    const int tile = blockIdx.y;   // 0..63
    const int c    = threadIdx.x;  // 0..255
    const int b    = tile >> 3;
    const int qt   = 8 + (tile & 7);

    const float inv = 1.0f / (g_lp[0][tile][row] + g_lp[1][tile][row]);
    const float o1 = g_Op[0][tile][row * 256 + c];
    const float o2 = g_Op[1][tile][row * 256 + c];
    out[((size_t)(b * TT + qt * 128 + row)) * HH + c] = (o1 + o2) * inv;
}

// ---------------------------------------------------------------------------
extern "C" void kernel_launch(void* const* d_in, const int* in_sizes, int n_in,
                              void* d_out, int out_size)
{
    const float* x  = (const float*)d_in[0];
    const float* Wq = (const float*)d_in[1];
    const float* bq = (const float*)d_in[2];
    const float* Wk = (const float*)d_in[3];
    const float* bk = (const float*)d_in[4];
    const float* Wv = (const float*)d_in[5];
    const float* bv = (const float*)d_in[6];
    float* out = (float*)d_out;

    const int proj_smem  = 2 * 128 * XP * 2;                    // ~68 KB (2 blocks/SM)
    const int flash_smem = (128 * QP + 4 * 64 * QP) * 2;        // ~198 KB

    cudaFuncSetAttribute(proj_kernel,  cudaFuncAttributeMaxDynamicSharedMemorySize, proj_smem);
    cudaFuncSetAttribute(flash_kernel, cudaFuncAttributeMaxDynamicSharedMemorySize, flash_smem);

    proj_kernel<<<dim3(2, 128), 256, proj_smem>>>(x, Wq, bq, Wk, bk, Wv, bv);
    flash_kernel<<<dim3(8, 24), 256, flash_smem>>>(out);
    combine_kernel<<<dim3(128, 64), 256>>>(out);
}